// round 2
// baseline (speedup 1.0000x reference)
#include <cuda_runtime.h>
#include <math.h>
#include <float.h>

#define NMAX 2048
#define HID  256
#define KMAX (NMAX/2)

// ---------------- scratch (device globals; no allocation allowed) ------------
__device__ float g_A[NMAX*NMAX];        // current adjacency (dense, symmetric)
__device__ float g_maskf[NMAX*NMAX];    // mask = (A!=0)|eye as float
__device__ float g_scoreT[NMAX*NMAX];   // scoreT[j][i] = score[i][j]
__device__ float g_SpT[KMAX*NMAX];      // SpT[q][i] = score[i][perm[q]]
__device__ float g_M2T[KMAX*NMAX];      // (SpT @ maskf)
__device__ float g_Ac[KMAX*KMAX];
__device__ float g_h[NMAX*HID];         // level input features (lvl>0)
__device__ float g_g[NMAX*HID];         // relu(gcn)
__device__ float g_xw[NMAX*HID];
__device__ float g_y[NMAX*HID];         // dinv-scaled xw
__device__ float g_S[NMAX*HID];         // A @ y
__device__ float g_mm[NMAX*HID];        // masked max
__device__ float g_xq[NMAX*HID];
__device__ float g_xnew[NMAX*HID];
__device__ float g_u[NMAX];
__device__ float g_v[NMAX];
__device__ float g_dinv[NMAX];
__device__ float g_av[NMAX];
__device__ float g_bv[NMAX];
__device__ float g_cv[NMAX];
__device__ float g_fit[NMAX];
__device__ float g_fvals[KMAX];
__device__ int   g_perm[KMAX];
__device__ float g_ro[2*HID];

// ---------------- tiled fp32 GEMM: C[M,N] = A[M,K] @ opB, opB = B or B^T ----
// Row-major. If TB: B is stored N x K row-major, logical B(k,n) = B[n*ldb+k].
// Requires: M%64==0, N%64==0, K%16==0, lda/ldb/ldc %4==0, 16B-aligned bases.
template<bool TB>
__global__ void __launch_bounds__(256) k_gemm(
    const float* __restrict__ A, const float* __restrict__ B, float* __restrict__ C,
    int M, int N, int K, int lda, int ldb, int ldc)
{
    __shared__ float As[16][64];
    __shared__ float Bs[16][64];
    const int tid = threadIdx.x;
    const int tx = tid & 15, ty = tid >> 4;
    const int m0 = blockIdx.y * 64, n0 = blockIdx.x * 64;
    const int ar = tid >> 2;            // 0..63
    const int ak = (tid & 3) << 2;      // 0,4,8,12
    const int bk = tid >> 4;            // 0..15 (for !TB)
    const int bn = (tid & 15) << 2;     // 0..60

    float acc[4][4];
#pragma unroll
    for (int i = 0; i < 4; i++)
#pragma unroll
        for (int j = 0; j < 4; j++) acc[i][j] = 0.f;

    for (int k0 = 0; k0 < K; k0 += 16) {
        float4 av = *(const float4*)(A + (size_t)(m0 + ar) * lda + (k0 + ak));
        As[ak+0][ar] = av.x; As[ak+1][ar] = av.y; As[ak+2][ar] = av.z; As[ak+3][ar] = av.w;
        if (TB) {
            float4 bv = *(const float4*)(B + (size_t)(n0 + ar) * ldb + (k0 + ak));
            Bs[ak+0][ar] = bv.x; Bs[ak+1][ar] = bv.y; Bs[ak+2][ar] = bv.z; Bs[ak+3][ar] = bv.w;
        } else {
            float4 bv = *(const float4*)(B + (size_t)(k0 + bk) * ldb + (n0 + bn));
            *(float4*)&Bs[bk][bn] = bv;
        }
        __syncthreads();
#pragma unroll
        for (int kk = 0; kk < 16; kk++) {
            float4 a4 = *(const float4*)&As[kk][ty << 2];
            float4 b4 = *(const float4*)&Bs[kk][tx << 2];
            acc[0][0] += a4.x * b4.x; acc[0][1] += a4.x * b4.y; acc[0][2] += a4.x * b4.z; acc[0][3] += a4.x * b4.w;
            acc[1][0] += a4.y * b4.x; acc[1][1] += a4.y * b4.y; acc[1][2] += a4.y * b4.z; acc[1][3] += a4.y * b4.w;
            acc[2][0] += a4.z * b4.x; acc[2][1] += a4.z * b4.y; acc[2][2] += a4.z * b4.z; acc[2][3] += a4.z * b4.w;
            acc[3][0] += a4.w * b4.x; acc[3][1] += a4.w * b4.y; acc[3][2] += a4.w * b4.z; acc[3][3] += a4.w * b4.w;
        }
        __syncthreads();
    }
#pragma unroll
    for (int i = 0; i < 4; i++) {
        float4 r; r.x = acc[i][0]; r.y = acc[i][1]; r.z = acc[i][2]; r.w = acc[i][3];
        *(float4*)(C + (size_t)(m0 + (ty << 2) + i) * ldc + n0 + (tx << 2)) = r;
    }
}

// ---------------- small kernels ---------------------------------------------
__global__ void k_zeroA(int n) {
    int i = blockIdx.x * blockDim.x + threadIdx.x;
    if (i < n * n) g_A[i] = 0.f;
    if (i < 2 * HID) g_ro[i] = 0.f;
}

__global__ void k_scatter(const int* __restrict__ ei, int ne, int n) {
    int e = blockIdx.x * blockDim.x + threadIdx.x;
    if (e < ne) g_A[(size_t)ei[e] * n + ei[ne + e]] = 1.0f;
}

__global__ void k_dinv(int n) {   // deg over row (A symmetric) + self loop
    int j = blockIdx.x, tid = threadIdx.x;
    __shared__ float red[256];
    const float* row = g_A + (size_t)j * n;
    float s = 0.f;
    for (int i = tid; i < n; i += 256) s += row[i];
    red[tid] = s; __syncthreads();
    for (int o = 128; o; o >>= 1) { if (tid < o) red[tid] += red[tid + o]; __syncthreads(); }
    if (tid == 0) g_dinv[j] = 1.0f / sqrtf(red[0] + 1.0f);
}

__global__ void k_scale(int n) {  // y = dinv[row] * xw
    int idx = blockIdx.x * blockDim.x + threadIdx.x;
    if (idx < n * HID) g_y[idx] = g_dinv[idx >> 8] * g_xw[idx];
}

__global__ void k_gcnepi(const float* __restrict__ bias, int n) {
    int idx = blockIdx.x * blockDim.x + threadIdx.x;
    if (idx < n * HID) {
        int row = idx >> 8, c = idx & 255;
        float val = g_dinv[row] * (g_S[idx] + g_y[idx]) + bias[c];
        g_g[idx] = fmaxf(val, 0.f);
    }
}

__global__ void k_maskf(int n) {
    int idx = blockIdx.x * blockDim.x + threadIdx.x;
    if (idx < n * n) {
        int i = idx / n, j = idx - i * n;
        g_maskf[idx] = (g_A[idx] != 0.f || i == j) ? 1.f : 0.f;
    }
}

__global__ void k_mmax(int n) {   // mm[j,c] = max over masked i of g[i,c]
    __shared__ float sm[NMAX];
    int j = blockIdx.x, c = threadIdx.x;
    const float* mrow = g_maskf + (size_t)j * n;
    for (int i = c; i < n; i += 256) sm[i] = mrow[i];
    __syncthreads();
    float m = -FLT_MAX;
    for (int i = 0; i < n; i++)
        if (sm[i] != 0.f) m = fmaxf(m, g_g[(size_t)i * HID + c]);
    g_mm[(size_t)j * HID + c] = m;
}

__global__ void k_uv(const float* __restrict__ linb, const float* __restrict__ attw, int n) {
    int w = (blockIdx.x * blockDim.x + threadIdx.x) >> 5;
    int lane = threadIdx.x & 31;
    if (w >= n) return;
    float su = 0.f, sv = 0.f;
    const float* xq = g_xq + (size_t)w * HID;
    const float* gg = g_g + (size_t)w * HID;
    for (int c = lane; c < HID; c += 32) {
        su += (xq[c] + linb[c]) * attw[c];
        sv += gg[c] * attw[HID + c];
    }
    for (int o = 16; o; o >>= 1) {
        su += __shfl_down_sync(0xffffffffu, su, o);
        sv += __shfl_down_sync(0xffffffffu, sv, o);
    }
    if (lane == 0) { g_u[w] = su; g_v[w] = sv; }
}

__global__ void k_softmax(const float* __restrict__ attb, int n) {
    int j = blockIdx.x, tid = threadIdx.x;
    __shared__ float red[256];
    __shared__ float s_mx, s_sum;
    const float* mrow = g_maskf + (size_t)j * n;
    float uj = g_u[j] + attb[0];
    // pass 1: max of leaky(v_i + u_j + b) over masked i
    float mx = -FLT_MAX;
    for (int i = tid; i < n; i += 256) {
        if (mrow[i] != 0.f) {
            float r = g_v[i] + uj; r = (r >= 0.f) ? r : 0.2f * r;
            mx = fmaxf(mx, r);
        }
    }
    red[tid] = mx; __syncthreads();
    for (int o = 128; o; o >>= 1) { if (tid < o) red[tid] = fmaxf(red[tid], red[tid + o]); __syncthreads(); }
    if (tid == 0) s_mx = red[0];
    __syncthreads();
    // pass 2: sum of exp
    float sm = 0.f;
    for (int i = tid; i < n; i += 256) {
        if (mrow[i] != 0.f) {
            float r = g_v[i] + uj; r = (r >= 0.f) ? r : 0.2f * r;
            sm += expf(r - s_mx);
        }
    }
    red[tid] = sm; __syncthreads();
    for (int o = 128; o; o >>= 1) { if (tid < o) red[tid] += red[tid + o]; __syncthreads(); }
    if (tid == 0) s_sum = red[0];
    __syncthreads();
    // pass 3: write scoreT row (0 for unmasked)
    float* srow = g_scoreT + (size_t)j * n;
    for (int i = tid; i < n; i += 256) {
        float val = 0.f;
        if (mrow[i] != 0.f) {
            float r = g_v[i] + uj; r = (r >= 0.f) ? r : 0.2f * r;
            val = expf(r - s_mx) / s_sum;
        }
        srow[i] = val;
    }
}

__global__ void k_abc(const float* __restrict__ le1W, const float* __restrict__ le1b,
                      const float* __restrict__ le2W, const float* __restrict__ le3W,
                      const float* __restrict__ le3b, int n) {
    int w = (blockIdx.x * blockDim.x + threadIdx.x) >> 5;
    int lane = threadIdx.x & 31;
    if (w >= n) return;
    const float* xr = g_xnew + (size_t)w * HID;
    float sa = 0.f, sb = 0.f, sc = 0.f;
    for (int c = lane; c < HID; c += 32) {
        float xv = xr[c];
        sa += xv * le1W[c]; sb += xv * le2W[c]; sc += xv * le3W[c];
    }
    for (int o = 16; o; o >>= 1) {
        sa += __shfl_down_sync(0xffffffffu, sa, o);
        sb += __shfl_down_sync(0xffffffffu, sb, o);
        sc += __shfl_down_sync(0xffffffffu, sc, o);
    }
    if (lane == 0) { g_av[w] = sa + le1b[0]; g_bv[w] = sb; g_cv[w] = sc + le3b[0]; }
}

__global__ void k_fit(int n) {
    int j = blockIdx.x, tid = threadIdx.x;
    __shared__ float rs[256], rc[256];
    const float* mrow = g_maskf + (size_t)j * n;
    float s = 0.f, cn = 0.f;
    for (int i = tid; i < n; i += 256) {
        float mf = mrow[i];
        s += mf * g_av[i]; cn += mf;
    }
    rs[tid] = s; rc[tid] = cn; __syncthreads();
    for (int o = 128; o; o >>= 1) {
        if (tid < o) { rs[tid] += rs[tid + o]; rc[tid] += rc[tid + o]; }
        __syncthreads();
    }
    if (tid == 0) {
        float z = rs[0] - rc[0] * g_bv[j] + g_cv[j];
        g_fit[j] = 1.0f / (1.0f + expf(-z));
    }
}

// bitonic sort descending by (fitness, then lower index first); n power of 2
__global__ void k_sort(int n, int k) {
    __shared__ float sv[NMAX];
    __shared__ int   si[NMAX];
    int tid = threadIdx.x;
    for (int i = tid; i < n; i += blockDim.x) { sv[i] = g_fit[i]; si[i] = i; }
    __syncthreads();
    for (int size = 2; size <= n; size <<= 1) {
        for (int stride = size >> 1; stride > 0; stride >>= 1) {
            for (int i = tid; i < n; i += blockDim.x) {
                int j = i ^ stride;
                if (j > i) {
                    bool descBlk = ((i & size) == 0);
                    float va = sv[i], vb = sv[j];
                    int ia = si[i], ib = si[j];
                    bool before = (va > vb) || (va == vb && ia < ib); // i ranks higher
                    bool dosw = descBlk ? (!before) : before;
                    if (dosw) { sv[i] = vb; sv[j] = va; si[i] = ib; si[j] = ia; }
                }
            }
            __syncthreads();
        }
    }
    for (int t = tid; t < k; t += blockDim.x) { g_perm[t] = si[t]; g_fvals[t] = sv[t]; }
}

__global__ void k_pool(int k) {
    int q = blockIdx.x, c = threadIdx.x;
    g_h[(size_t)q * HID + c] = g_xnew[(size_t)g_perm[q] * HID + c] * g_fvals[q];
}

__global__ void k_readout(int k) {  // one block, 256 threads
    int c = threadIdx.x;
    float s = 0.f, m = -FLT_MAX;
    for (int q = 0; q < k; q++) {
        float v = g_h[(size_t)q * HID + c];
        s += v; m = fmaxf(m, v);
    }
    g_ro[c] += s / (float)k;
    g_ro[HID + c] += m;
}

__global__ void k_gatherSpT(int n, int k) {
    int i = blockIdx.x * 256 + threadIdx.x;
    int q = blockIdx.y;
    g_SpT[(size_t)q * n + i] = g_scoreT[(size_t)g_perm[q] * n + i];
}

__global__ void k_setA(int k) {  // A <- Ac with zero diagonal
    int idx = blockIdx.x * blockDim.x + threadIdx.x;
    if (idx < k * k) {
        int p = idx / k, q = idx - p * k;
        g_A[idx] = (p == q) ? 0.f : g_Ac[idx];
    }
}

__global__ void k_head(const float* __restrict__ l1W, const float* __restrict__ l1b,
                       const float* __restrict__ l2W, const float* __restrict__ l2b,
                       float* __restrict__ out) {
    __shared__ float hid[HID];
    __shared__ float lg[16];
    int t = threadIdx.x;  // 256 threads
    float s = l1b[t];
    for (int kk = 0; kk < 2 * HID; kk++) s += g_ro[kk] * l1W[kk * HID + t];
    hid[t] = fmaxf(s, 0.f);
    __syncthreads();
    if (t < 10) {
        float s2 = l2b[t];
        for (int c = 0; c < HID; c++) s2 += hid[c] * l2W[c * 10 + t];
        lg[t] = s2;
    }
    __syncthreads();
    if (t == 0) {
        float m = lg[0];
        for (int i = 1; i < 10; i++) m = fmaxf(m, lg[i]);
        float sm = 0.f;
        for (int i = 0; i < 10; i++) sm += expf(lg[i] - m);
        float ls = logf(sm);
        for (int i = 0; i < 10; i++) out[i] = lg[i] - m - ls;
    }
}

// ---------------- launcher ---------------------------------------------------
extern "C" void kernel_launch(void* const* d_in, const int* in_sizes, int n_in,
                              void* d_out, int out_size) {
    const float* x    = (const float*)d_in[0];
    const int*   ei   = (const int*)d_in[1];
    const float* W1   = (const float*)d_in[2];
    const float* b1   = (const float*)d_in[3];
    const float* W2   = (const float*)d_in[4];
    const float* b2   = (const float*)d_in[5];
    const float* linW = (const float*)d_in[6];
    const float* linb = (const float*)d_in[7];
    const float* attw = (const float*)d_in[8];
    const float* attb = (const float*)d_in[9];
    const float* le1W = (const float*)d_in[10];
    const float* le1b = (const float*)d_in[11];
    const float* le2W = (const float*)d_in[12];
    const float* le3W = (const float*)d_in[13];
    const float* le3b = (const float*)d_in[14];
    const float* l1W  = (const float*)d_in[15];
    const float* l1b  = (const float*)d_in[16];
    const float* l2W  = (const float*)d_in[17];
    const float* l2b  = (const float*)d_in[18];

    float *pA, *pmask, *pscoreT, *pSpT, *pM2T, *pAc;
    float *pxw, *py, *pS, *pmm, *pxq, *pxnew, *ph;
    cudaGetSymbolAddress((void**)&pA, g_A);
    cudaGetSymbolAddress((void**)&pmask, g_maskf);
    cudaGetSymbolAddress((void**)&pscoreT, g_scoreT);
    cudaGetSymbolAddress((void**)&pSpT, g_SpT);
    cudaGetSymbolAddress((void**)&pM2T, g_M2T);
    cudaGetSymbolAddress((void**)&pAc, g_Ac);
    cudaGetSymbolAddress((void**)&pxw, g_xw);
    cudaGetSymbolAddress((void**)&py, g_y);
    cudaGetSymbolAddress((void**)&pS, g_S);
    cudaGetSymbolAddress((void**)&pmm, g_mm);
    cudaGetSymbolAddress((void**)&pxq, g_xq);
    cudaGetSymbolAddress((void**)&pxnew, g_xnew);
    cudaGetSymbolAddress((void**)&ph, g_h);
    float* pg;
    cudaGetSymbolAddress((void**)&pg, g_g);

    int n = 2048;
    int ne = in_sizes[1] / 2;

    k_zeroA<<<(n * n + 255) / 256, 256>>>(n);
    k_scatter<<<(ne + 255) / 256, 256>>>(ei, ne, n);

    const float* X = x;
    int f_in = 128;

    for (int lvl = 0; lvl < 3; lvl++) {
        const float* W  = lvl ? W2 : W1;
        const float* bb = lvl ? b2 : b1;
        int k = n / 2;
        dim3 gfeat(HID / 64, n / 64);

        // GCN: g = relu(dinv*(A@(dinv*xW) + dinv*xW) + b)
        k_gemm<false><<<gfeat, 256>>>(X, W, pxw, n, HID, f_in, f_in, HID, HID);
        k_dinv<<<n, 256>>>(n);
        k_scale<<<(n * HID + 255) / 256, 256>>>(n);
        k_gemm<false><<<gfeat, 256>>>(pA, py, pS, n, HID, n, n, HID, HID);
        k_gcnepi<<<(n * HID + 255) / 256, 256>>>(bb, n);

        // ASAP attention
        k_maskf<<<(n * n + 255) / 256, 256>>>(n);
        k_mmax<<<n, 256>>>(n);
        k_gemm<false><<<gfeat, 256>>>(pmm, linW, pxq, n, HID, HID, HID, HID, HID);
        k_uv<<<(n * 32 + 255) / 256, 256>>>(linb, attw, n);
        k_softmax<<<n, 256>>>(attb, n);
        k_gemm<false><<<gfeat, 256>>>(pscoreT, pg, pxnew, n, HID, n, n, HID, HID);

        // fitness + top-k pooling
        k_abc<<<(n * 32 + 255) / 256, 256>>>(le1W, le1b, le2W, le3W, le3b, n);
        k_fit<<<n, 256>>>(n);
        k_sort<<<1, 1024>>>(n, k);
        k_pool<<<k, 256>>>(k);
        k_readout<<<1, 256>>>(k);

        if (lvl < 2) {  // coarsened adjacency only needed for next level
            k_gatherSpT<<<dim3(n / 256, k), 256>>>(n, k);
            k_gemm<false><<<dim3(n / 64, k / 64), 256>>>(pSpT, pmask, pM2T, k, n, n, n, n, n);
            k_gemm<true><<<dim3(k / 64, k / 64), 256>>>(pSpT, pM2T, pAc, k, k, n, n, n, k);
            k_setA<<<(k * k + 255) / 256, 256>>>(k);
        }

        X = ph; f_in = HID; n = k;
    }

    k_head<<<1, 256>>>(l1W, l1b, l2W, l2b, (float*)d_out);
}

// round 9
// speedup vs baseline: 2.0393x; 2.0393x over previous
#include <cuda_runtime.h>
#include <math.h>
#include <float.h>

#define NMAX 2048
#define HID  256
#define KMAX (NMAX/2)
#define CAP  256

// ---------------- scratch (device globals) -----------------------------------
__device__ float g_A[NMAX*NMAX];        // current adjacency (dense, symmetric)
__device__ float g_maskf[NMAX*NMAX];    // lvl>=1: mask = (A!=0)|eye
__device__ float g_scoreT[NMAX*NMAX];   // lvl>=1: scoreT[j][i] = score[i][j]
__device__ float g_SpT[KMAX*NMAX];      // lvl0: Sp dense [n x k]; lvl1: SpT [k x n]
__device__ float g_M2T[KMAX*NMAX];      // lvl0: M2 [n x k]; lvl1: SpT@mask
__device__ float g_Ac[KMAX*KMAX];
__device__ float g_h[NMAX*HID];
__device__ float g_g[NMAX*HID];
__device__ float g_xw[NMAX*HID];
__device__ float g_y[NMAX*HID];
__device__ float g_S[NMAX*HID];
__device__ float g_mm[NMAX*HID];
__device__ float g_xq[NMAX*HID];
__device__ float g_xnew[NMAX*HID];
__device__ float g_u[NMAX];
__device__ float g_v[NMAX];
__device__ float g_dinv[NMAX];
__device__ float g_av[NMAX];
__device__ float g_bv[NMAX];
__device__ float g_cv[NMAX];
__device__ float g_fit[NMAX];
__device__ float g_fvals[KMAX];
__device__ int   g_perm[KMAX];
__device__ float g_ro[2*HID];
__device__ int   g_nzidx[NMAX*CAP];
__device__ int   g_nzcnt[NMAX];
__device__ float g_sval[NMAX*CAP];

// ---------------- tiled fp32 GEMM / masked-max --------------------------------
// OP=0: C = A@B (or A@B^T if TB). OP=1: C[m][n] = max over k where A[m][k]!=0 of B[k][n]
template<bool TB, int OP>
__global__ void __launch_bounds__(256) k_gemm(
    const float* __restrict__ A, const float* __restrict__ B, float* __restrict__ C,
    int M, int N, int K, int lda, int ldb, int ldc)
{
    __shared__ float As[16][64];
    __shared__ float Bs[16][64];
    const int tid = threadIdx.x;
    const int tx = tid & 15, ty = tid >> 4;
    const int m0 = blockIdx.y * 64, n0 = blockIdx.x * 64;
    const int ar = tid >> 2;
    const int ak = (tid & 3) << 2;
    const int bk = tid >> 4;
    const int bn = (tid & 15) << 2;

    float acc[4][4];
#pragma unroll
    for (int i = 0; i < 4; i++)
#pragma unroll
        for (int j = 0; j < 4; j++) acc[i][j] = OP ? -FLT_MAX : 0.f;

    for (int k0 = 0; k0 < K; k0 += 16) {
        float4 av = *(const float4*)(A + (size_t)(m0 + ar) * lda + (k0 + ak));
        As[ak+0][ar] = av.x; As[ak+1][ar] = av.y; As[ak+2][ar] = av.z; As[ak+3][ar] = av.w;
        if (TB) {
            float4 bv = *(const float4*)(B + (size_t)(n0 + ar) * ldb + (k0 + ak));
            Bs[ak+0][ar] = bv.x; Bs[ak+1][ar] = bv.y; Bs[ak+2][ar] = bv.z; Bs[ak+3][ar] = bv.w;
        } else {
            float4 bv = *(const float4*)(B + (size_t)(k0 + bk) * ldb + (n0 + bn));
            *(float4*)&Bs[bk][bn] = bv;
        }
        __syncthreads();
#pragma unroll
        for (int kk = 0; kk < 16; kk++) {
            float4 a4 = *(const float4*)&As[kk][ty << 2];
            float4 b4 = *(const float4*)&Bs[kk][tx << 2];
            if (OP == 0) {
                acc[0][0] += a4.x * b4.x; acc[0][1] += a4.x * b4.y; acc[0][2] += a4.x * b4.z; acc[0][3] += a4.x * b4.w;
                acc[1][0] += a4.y * b4.x; acc[1][1] += a4.y * b4.y; acc[1][2] += a4.y * b4.z; acc[1][3] += a4.y * b4.w;
                acc[2][0] += a4.z * b4.x; acc[2][1] += a4.z * b4.y; acc[2][2] += a4.z * b4.z; acc[2][3] += a4.z * b4.w;
                acc[3][0] += a4.w * b4.x; acc[3][1] += a4.w * b4.y; acc[3][2] += a4.w * b4.z; acc[3][3] += a4.w * b4.w;
            } else {
                float am[4] = {a4.x, a4.y, a4.z, a4.w};
                float bm[4] = {b4.x, b4.y, b4.z, b4.w};
#pragma unroll
                for (int i = 0; i < 4; i++)
#pragma unroll
                    for (int j = 0; j < 4; j++)
                        acc[i][j] = (am[i] != 0.f) ? fmaxf(acc[i][j], bm[j]) : acc[i][j];
            }
        }
        __syncthreads();
    }
#pragma unroll
    for (int i = 0; i < 4; i++) {
        float4 r; r.x = acc[i][0]; r.y = acc[i][1]; r.z = acc[i][2]; r.w = acc[i][3];
        *(float4*)(C + (size_t)(m0 + (ty << 2) + i) * ldc + n0 + (tx << 2)) = r;
    }
}

// ---------------- level-0 sparse kernels --------------------------------------
__global__ void k_scatter(const int* __restrict__ ei, int ne, int n) {
    int e = blockIdx.x * blockDim.x + threadIdx.x;
    if (e < ne) g_A[(size_t)ei[e] * n + ei[ne + e]] = 1.0f;
}

// warp per row: compact nonzero indices (A row, diag forced) in ascending order
__global__ void k_buildnz(int n) {
    int w = threadIdx.x >> 5, lane = threadIdx.x & 31;
    int j = blockIdx.x * 8 + w;
    if (j >= n) return;
    const float* row = g_A + (size_t)j * n;
    int* idx = g_nzidx + (size_t)j * CAP;
    int cnt = 0;
    for (int c0 = 0; c0 < n; c0 += 32) {
        int i = c0 + lane;
        bool p = (row[i] != 0.f) || (i == j);
        unsigned m = __ballot_sync(0xffffffffu, p);
        int pos = cnt + __popc(m & ((1u << lane) - 1u));
        if (p && pos < CAP) idx[pos] = i;
        cnt += __popc(m);
    }
    if (cnt > CAP) cnt = CAP;
    if (lane == 0) {
        g_nzcnt[j] = cnt;
        g_dinv[j] = 1.0f / sqrtf((float)cnt);   // A values all 1 -> deg == cnt
    }
}

__global__ void k_scale(int n) {  // y = dinv[row] * xw
    int idx = blockIdx.x * blockDim.x + threadIdx.x;
    if (idx < n * HID) g_y[idx] = g_dinv[idx >> 8] * g_xw[idx];
}

// g[j] = relu(dinv[j] * sum_{i in nz(j)} y[i] + b)
__global__ void k_gcn_gather(const float* __restrict__ bias) {
    __shared__ int sidx[CAP];
    int j = blockIdx.x, c = threadIdx.x;
    int cnt = g_nzcnt[j];
    const int* idx = g_nzidx + (size_t)j * CAP;
    for (int t = c; t < cnt; t += 256) sidx[t] = idx[t];
    __syncthreads();
    float acc = 0.f;
#pragma unroll 4
    for (int t = 0; t < cnt; t++) acc += g_y[(size_t)sidx[t] * HID + c];
    g_g[(size_t)j * HID + c] = fmaxf(g_dinv[j] * acc + bias[c], 0.f);
}

// mm[j] = max_{i in nz(j)} g[i]
__global__ void k_max_gather() {
    __shared__ int sidx[CAP];
    int j = blockIdx.x, c = threadIdx.x;
    int cnt = g_nzcnt[j];
    const int* idx = g_nzidx + (size_t)j * CAP;
    for (int t = c; t < cnt; t += 256) sidx[t] = idx[t];
    __syncthreads();
    float m = -FLT_MAX;
#pragma unroll 4
    for (int t = 0; t < cnt; t++) m = fmaxf(m, g_g[(size_t)sidx[t] * HID + c]);
    g_mm[(size_t)j * HID + c] = m;
}

__global__ void k_uv(const float* __restrict__ linb, const float* __restrict__ attw, int n) {
    int w = (blockIdx.x * blockDim.x + threadIdx.x) >> 5;
    int lane = threadIdx.x & 31;
    if (w >= n) return;
    float su = 0.f, sv = 0.f;
    const float* xq = g_xq + (size_t)w * HID;
    const float* gg = g_g + (size_t)w * HID;
    for (int c = lane; c < HID; c += 32) {
        su += (xq[c] + linb[c]) * attw[c];
        sv += gg[c] * attw[HID + c];
    }
    for (int o = 16; o; o >>= 1) {
        su += __shfl_down_sync(0xffffffffu, su, o);
        sv += __shfl_down_sync(0xffffffffu, sv, o);
    }
    if (lane == 0) { g_u[w] = su; g_v[w] = sv; }
}

// softmax over nz list, store values aligned with list
__global__ void k_softmax_nz(const float* __restrict__ attb, int n) {
    int w = threadIdx.x >> 5, lane = threadIdx.x & 31;
    int j = blockIdx.x * 8 + w;
    if (j >= n) return;
    int cnt = g_nzcnt[j];
    const int* idx = g_nzidx + (size_t)j * CAP;
    float uj = g_u[j] + attb[0];
    float mx = -FLT_MAX;
    for (int t = lane; t < cnt; t += 32) {
        float r = g_v[idx[t]] + uj; r = (r >= 0.f) ? r : 0.2f * r;
        mx = fmaxf(mx, r);
    }
    for (int o = 16; o; o >>= 1) mx = fmaxf(mx, __shfl_xor_sync(0xffffffffu, mx, o));
    float sm = 0.f;
    for (int t = lane; t < cnt; t += 32) {
        float r = g_v[idx[t]] + uj; r = (r >= 0.f) ? r : 0.2f * r;
        sm += expf(r - mx);
    }
    for (int o = 16; o; o >>= 1) sm += __shfl_xor_sync(0xffffffffu, sm, o);
    float* sval = g_sval + (size_t)j * CAP;
    for (int t = lane; t < cnt; t += 32) {
        float r = g_v[idx[t]] + uj; r = (r >= 0.f) ? r : 0.2f * r;
        sval[t] = expf(r - mx) / sm;
    }
}

// xnew[j] = sum_t sval[j][t] * g[idx[j][t]]
__global__ void k_wsum_gather() {
    __shared__ int sidx[CAP];
    __shared__ float sw[CAP];
    int j = blockIdx.x, c = threadIdx.x;
    int cnt = g_nzcnt[j];
    const int* idx = g_nzidx + (size_t)j * CAP;
    const float* sv = g_sval + (size_t)j * CAP;
    for (int t = c; t < cnt; t += 256) { sidx[t] = idx[t]; sw[t] = sv[t]; }
    __syncthreads();
    float acc = 0.f;
#pragma unroll 4
    for (int t = 0; t < cnt; t++) acc += sw[t] * g_g[(size_t)sidx[t] * HID + c];
    g_xnew[(size_t)j * HID + c] = acc;
}

__global__ void k_abc(const float* __restrict__ le1W, const float* __restrict__ le1b,
                      const float* __restrict__ le2W, const float* __restrict__ le3W,
                      const float* __restrict__ le3b, int n) {
    int w = (blockIdx.x * blockDim.x + threadIdx.x) >> 5;
    int lane = threadIdx.x & 31;
    if (w >= n) return;
    const float* xr = g_xnew + (size_t)w * HID;
    float sa = 0.f, sb = 0.f, sc = 0.f;
    for (int c = lane; c < HID; c += 32) {
        float xv = xr[c];
        sa += xv * le1W[c]; sb += xv * le2W[c]; sc += xv * le3W[c];
    }
    for (int o = 16; o; o >>= 1) {
        sa += __shfl_down_sync(0xffffffffu, sa, o);
        sb += __shfl_down_sync(0xffffffffu, sb, o);
        sc += __shfl_down_sync(0xffffffffu, sc, o);
    }
    if (lane == 0) { g_av[w] = sa + le1b[0]; g_bv[w] = sb; g_cv[w] = sc + le3b[0]; }
}

__global__ void k_fit_nz(int n) {
    int w = threadIdx.x >> 5, lane = threadIdx.x & 31;
    int j = blockIdx.x * 8 + w;
    if (j >= n) return;
    int cnt = g_nzcnt[j];
    const int* idx = g_nzidx + (size_t)j * CAP;
    float s = 0.f;
    for (int t = lane; t < cnt; t += 32) s += g_av[idx[t]];
    for (int o = 16; o; o >>= 1) s += __shfl_xor_sync(0xffffffffu, s, o);
    if (lane == 0) {
        float z = s - (float)cnt * g_bv[j] + g_cv[j];
        g_fit[j] = 1.0f / (1.0f + expf(-z));
    }
}

// Sp dense scatter: Sp[i][q] = score[i][perm[q]]
__global__ void k_spscatter(int k) {
    int q = blockIdx.x, t = threadIdx.x;
    int pj = g_perm[q];
    if (t < g_nzcnt[pj])
        g_SpT[(size_t)g_nzidx[(size_t)pj * CAP + t] * k + q] = g_sval[(size_t)pj * CAP + t];
}

// M2[j][:] = sum_{i in nz(j)} Sp[i][:]   (k = row stride in FLOATS; 256 thr = k/4 float4)
__global__ void k_m2(int k) {
    __shared__ int sidx[CAP];
    int j = blockIdx.x, c = threadIdx.x;
    int cnt = g_nzcnt[j];
    const int* idx = g_nzidx + (size_t)j * CAP;
    for (int t = c; t < cnt; t += 256) sidx[t] = idx[t];
    __syncthreads();
    float4 acc = {0.f, 0.f, 0.f, 0.f};
#pragma unroll 2
    for (int t = 0; t < cnt; t++) {
        float4 v = ((const float4*)(g_SpT + (size_t)sidx[t] * k))[c];
        acc.x += v.x; acc.y += v.y; acc.z += v.z; acc.w += v.w;
    }
    ((float4*)(g_M2T + (size_t)j * k))[c] = acc;
}

// Ac[p][:] = sum_t sval[perm[p]][t] * M2[idx[perm[p]][t]][:]   (k = row stride floats)
__global__ void k_acg(int k) {
    __shared__ int sidx[CAP];
    __shared__ float sw[CAP];
    int p = blockIdx.x, c = threadIdx.x;
    int pp = g_perm[p];
    int cnt = g_nzcnt[pp];
    const int* idx = g_nzidx + (size_t)pp * CAP;
    const float* sv = g_sval + (size_t)pp * CAP;
    for (int t = c; t < cnt; t += 256) { sidx[t] = idx[t]; sw[t] = sv[t]; }
    __syncthreads();
    float4 acc = {0.f, 0.f, 0.f, 0.f};
#pragma unroll 2
    for (int t = 0; t < cnt; t++) {
        float w = sw[t];
        float4 v = ((const float4*)(g_M2T + (size_t)sidx[t] * k))[c];
        acc.x += w * v.x; acc.y += w * v.y; acc.z += w * v.z; acc.w += w * v.w;
    }
    ((float4*)(g_Ac + (size_t)p * k))[c] = acc;
}

// ---------------- dense-path kernels (levels >= 1) ---------------------------
__global__ void k_dinv(int n) {
    int j = blockIdx.x, tid = threadIdx.x;
    __shared__ float red[256];
    const float* row = g_A + (size_t)j * n;
    float s = 0.f;
    for (int i = tid; i < n; i += 256) s += row[i];
    red[tid] = s; __syncthreads();
    for (int o = 128; o; o >>= 1) { if (tid < o) red[tid] += red[tid + o]; __syncthreads(); }
    if (tid == 0) g_dinv[j] = 1.0f / sqrtf(red[0] + 1.0f);
}

__global__ void k_gcnepi(const float* __restrict__ bias, int n) {
    int idx = blockIdx.x * blockDim.x + threadIdx.x;
    if (idx < n * HID) {
        int row = idx >> 8, c = idx & 255;
        float val = g_dinv[row] * (g_S[idx] + g_y[idx]) + bias[c];
        g_g[idx] = fmaxf(val, 0.f);
    }
}

__global__ void k_maskf(int n) {
    int idx = blockIdx.x * blockDim.x + threadIdx.x;
    if (idx < n * n) {
        int i = idx / n, j = idx - i * n;
        g_maskf[idx] = (g_A[idx] != 0.f || i == j) ? 1.f : 0.f;
    }
}

__global__ void k_softmax(const float* __restrict__ attb, int n) {
    int j = blockIdx.x, tid = threadIdx.x;
    __shared__ float red[256];
    __shared__ float s_mx, s_sum;
    const float* mrow = g_maskf + (size_t)j * n;
    float uj = g_u[j] + attb[0];
    float mx = -FLT_MAX;
    for (int i = tid; i < n; i += 256) {
        if (mrow[i] != 0.f) {
            float r = g_v[i] + uj; r = (r >= 0.f) ? r : 0.2f * r;
            mx = fmaxf(mx, r);
        }
    }
    red[tid] = mx; __syncthreads();
    for (int o = 128; o; o >>= 1) { if (tid < o) red[tid] = fmaxf(red[tid], red[tid + o]); __syncthreads(); }
    if (tid == 0) s_mx = red[0];
    __syncthreads();
    float sm = 0.f;
    for (int i = tid; i < n; i += 256) {
        if (mrow[i] != 0.f) {
            float r = g_v[i] + uj; r = (r >= 0.f) ? r : 0.2f * r;
            sm += expf(r - s_mx);
        }
    }
    red[tid] = sm; __syncthreads();
    for (int o = 128; o; o >>= 1) { if (tid < o) red[tid] += red[tid + o]; __syncthreads(); }
    if (tid == 0) s_sum = red[0];
    __syncthreads();
    float* srow = g_scoreT + (size_t)j * n;
    for (int i = tid; i < n; i += 256) {
        float val = 0.f;
        if (mrow[i] != 0.f) {
            float r = g_v[i] + uj; r = (r >= 0.f) ? r : 0.2f * r;
            val = expf(r - s_mx) / s_sum;
        }
        srow[i] = val;
    }
}

__global__ void k_fit(int n) {
    int j = blockIdx.x, tid = threadIdx.x;
    __shared__ float rs[256], rc[256];
    const float* mrow = g_maskf + (size_t)j * n;
    float s = 0.f, cn = 0.f;
    for (int i = tid; i < n; i += 256) {
        float mf = mrow[i];
        s += mf * g_av[i]; cn += mf;
    }
    rs[tid] = s; rc[tid] = cn; __syncthreads();
    for (int o = 128; o; o >>= 1) {
        if (tid < o) { rs[tid] += rs[tid + o]; rc[tid] += rc[tid + o]; }
        __syncthreads();
    }
    if (tid == 0) {
        float z = rs[0] - rc[0] * g_bv[j] + g_cv[j];
        g_fit[j] = 1.0f / (1.0f + expf(-z));
    }
}

__global__ void k_sort(int n, int k) {
    __shared__ float sv[NMAX];
    __shared__ int   si[NMAX];
    int tid = threadIdx.x;
    for (int i = tid; i < n; i += blockDim.x) { sv[i] = g_fit[i]; si[i] = i; }
    __syncthreads();
    for (int size = 2; size <= n; size <<= 1) {
        for (int stride = size >> 1; stride > 0; stride >>= 1) {
            for (int i = tid; i < n; i += blockDim.x) {
                int j = i ^ stride;
                if (j > i) {
                    bool descBlk = ((i & size) == 0);
                    float va = sv[i], vb = sv[j];
                    int ia = si[i], ib = si[j];
                    bool before = (va > vb) || (va == vb && ia < ib);
                    bool dosw = descBlk ? (!before) : before;
                    if (dosw) { sv[i] = vb; sv[j] = va; si[i] = ib; si[j] = ia; }
                }
            }
            __syncthreads();
        }
    }
    for (int t = tid; t < k; t += blockDim.x) { g_perm[t] = si[t]; g_fvals[t] = sv[t]; }
}

__global__ void k_pool(int k) {
    int q = blockIdx.x, c = threadIdx.x;
    g_h[(size_t)q * HID + c] = g_xnew[(size_t)g_perm[q] * HID + c] * g_fvals[q];
}

__global__ void k_readout(int k) {
    int c = threadIdx.x;
    float s = 0.f, m = -FLT_MAX;
    for (int q = 0; q < k; q++) {
        float v = g_h[(size_t)q * HID + c];
        s += v; m = fmaxf(m, v);
    }
    g_ro[c] += s / (float)k;
    g_ro[HID + c] += m;
}

__global__ void k_gatherSpT(int n, int k) {
    int i = blockIdx.x * 256 + threadIdx.x;
    int q = blockIdx.y;
    g_SpT[(size_t)q * n + i] = g_scoreT[(size_t)g_perm[q] * n + i];
}

__global__ void k_setA(int k) {
    int idx = blockIdx.x * blockDim.x + threadIdx.x;
    if (idx < k * k) {
        int p = idx / k, q = idx - p * k;
        g_A[idx] = (p == q) ? 0.f : g_Ac[idx];
    }
}

__global__ void k_head(const float* __restrict__ l1W, const float* __restrict__ l1b,
                       const float* __restrict__ l2W, const float* __restrict__ l2b,
                       float* __restrict__ out) {
    __shared__ float hid[HID];
    __shared__ float lg[16];
    int t = threadIdx.x;
    float s = l1b[t];
    for (int kk = 0; kk < 2 * HID; kk++) s += g_ro[kk] * l1W[kk * HID + t];
    hid[t] = fmaxf(s, 0.f);
    __syncthreads();
    if (t < 10) {
        float s2 = l2b[t];
        for (int c = 0; c < HID; c++) s2 += hid[c] * l2W[c * 10 + t];
        lg[t] = s2;
    }
    __syncthreads();
    if (t == 0) {
        float m = lg[0];
        for (int i = 1; i < 10; i++) m = fmaxf(m, lg[i]);
        float sm = 0.f;
        for (int i = 0; i < 10; i++) sm += expf(lg[i] - m);
        float ls = logf(sm);
        for (int i = 0; i < 10; i++) out[i] = lg[i] - m - ls;
    }
}

// ---------------- launcher ---------------------------------------------------
extern "C" void kernel_launch(void* const* d_in, const int* in_sizes, int n_in,
                              void* d_out, int out_size) {
    const float* x    = (const float*)d_in[0];
    const int*   ei   = (const int*)d_in[1];
    const float* W1   = (const float*)d_in[2];
    const float* b1   = (const float*)d_in[3];
    const float* W2   = (const float*)d_in[4];
    const float* b2   = (const float*)d_in[5];
    const float* linW = (const float*)d_in[6];
    const float* linb = (const float*)d_in[7];
    const float* attw = (const float*)d_in[8];
    const float* attb = (const float*)d_in[9];
    const float* le1W = (const float*)d_in[10];
    const float* le1b = (const float*)d_in[11];
    const float* le2W = (const float*)d_in[12];
    const float* le3W = (const float*)d_in[13];
    const float* le3b = (const float*)d_in[14];
    const float* l1W  = (const float*)d_in[15];
    const float* l1b  = (const float*)d_in[16];
    const float* l2W  = (const float*)d_in[17];
    const float* l2b  = (const float*)d_in[18];

    float *pA, *pmask, *pscoreT, *pSpT, *pM2T, *pAc, *pxw, *py, *pS, *pmm, *pxq, *pxnew, *ph, *pg, *pro;
    cudaGetSymbolAddress((void**)&pA, g_A);
    cudaGetSymbolAddress((void**)&pmask, g_maskf);
    cudaGetSymbolAddress((void**)&pscoreT, g_scoreT);
    cudaGetSymbolAddress((void**)&pSpT, g_SpT);
    cudaGetSymbolAddress((void**)&pM2T, g_M2T);
    cudaGetSymbolAddress((void**)&pAc, g_Ac);
    cudaGetSymbolAddress((void**)&pxw, g_xw);
    cudaGetSymbolAddress((void**)&py, g_y);
    cudaGetSymbolAddress((void**)&pS, g_S);
    cudaGetSymbolAddress((void**)&pmm, g_mm);
    cudaGetSymbolAddress((void**)&pxq, g_xq);
    cudaGetSymbolAddress((void**)&pxnew, g_xnew);
    cudaGetSymbolAddress((void**)&ph, g_h);
    cudaGetSymbolAddress((void**)&pg, g_g);
    cudaGetSymbolAddress((void**)&pro, g_ro);

    int n = 2048;
    int ne = in_sizes[1] / 2;

    cudaMemsetAsync(pA, 0, (size_t)n * n * sizeof(float));
    cudaMemsetAsync(pro, 0, 2 * HID * sizeof(float));
    k_scatter<<<(ne + 255) / 256, 256>>>(ei, ne, n);

    const float* X = x;
    int f_in = 128;

    for (int lvl = 0; lvl < 3; lvl++) {
        const float* W  = lvl ? W2 : W1;
        const float* bb = lvl ? b2 : b1;
        int k = n / 2;
        dim3 gfeat(HID / 64, n / 64);

        if (lvl == 0) {
            // ---- sparse level-0 path ----
            k_gemm<false,0><<<gfeat, 256>>>(X, W, pxw, n, HID, f_in, f_in, HID, HID);
            k_buildnz<<<n / 8, 256>>>(n);                  // nz lists + dinv
            k_scale<<<(n * HID + 255) / 256, 256>>>(n);
            k_gcn_gather<<<n, 256>>>(bb);                  // g = relu(dinv*A1@y + b)
            k_max_gather<<<n, 256>>>();                    // masked max
            k_gemm<false,0><<<gfeat, 256>>>(pmm, linW, pxq, n, HID, HID, HID, HID, HID);
            k_uv<<<(n * 32 + 255) / 256, 256>>>(linb, attw, n);
            k_softmax_nz<<<n / 8, 256>>>(attb, n);
            k_wsum_gather<<<n, 256>>>();                   // xnew
            k_abc<<<(n * 32 + 255) / 256, 256>>>(le1W, le1b, le2W, le3W, le3b, n);
            k_fit_nz<<<n / 8, 256>>>(n);
            k_sort<<<1, 1024>>>(n, k);
            k_pool<<<k, 256>>>(k);
            k_readout<<<1, 256>>>(k);
            // coarsen: Sp dense, M2 = mask@Sp (row gathers), Ac = Sp^T@M2
            cudaMemsetAsync(pSpT, 0, (size_t)n * k * sizeof(float));
            k_spscatter<<<k, 256>>>(k);
            k_m2<<<n, 256>>>(k);       // k = row stride in floats; 256 thr * float4 covers k=1024
            k_acg<<<k, 256>>>(k);
            k_setA<<<(k * k + 255) / 256, 256>>>(k);
        } else {
            // ---- dense path ----
            k_gemm<false,0><<<gfeat, 256>>>(X, W, pxw, n, HID, f_in, f_in, HID, HID);
            k_dinv<<<n, 256>>>(n);
            k_scale<<<(n * HID + 255) / 256, 256>>>(n);
            k_gemm<false,0><<<gfeat, 256>>>(pA, py, pS, n, HID, n, n, HID, HID);
            k_gcnepi<<<(n * HID + 255) / 256, 256>>>(bb, n);

            k_maskf<<<(n * n + 255) / 256, 256>>>(n);
            k_gemm<false,1><<<gfeat, 256>>>(pmask, pg, pmm, n, HID, n, n, HID, HID);
            k_gemm<false,0><<<gfeat, 256>>>(pmm, linW, pxq, n, HID, HID, HID, HID, HID);
            k_uv<<<(n * 32 + 255) / 256, 256>>>(linb, attw, n);
            k_softmax<<<n, 256>>>(attb, n);
            k_gemm<false,0><<<gfeat, 256>>>(pscoreT, pg, pxnew, n, HID, n, n, HID, HID);

            k_abc<<<(n * 32 + 255) / 256, 256>>>(le1W, le1b, le2W, le3W, le3b, n);
            k_fit<<<n, 256>>>(n);
            k_sort<<<1, 1024>>>(n, k);
            k_pool<<<k, 256>>>(k);
            k_readout<<<1, 256>>>(k);

            if (lvl < 2) {
                k_gatherSpT<<<dim3(n / 256, k), 256>>>(n, k);
                k_gemm<false,0><<<dim3(n / 64, k / 64), 256>>>(pSpT, pmask, pM2T, k, n, n, n, n, n);
                k_gemm<true,0><<<dim3(k / 64, k / 64), 256>>>(pSpT, pM2T, pAc, k, k, n, n, n, k);
                k_setA<<<(k * k + 255) / 256, 256>>>(k);
            }
        }

        X = ph; f_in = HID; n = k;
    }

    k_head<<<1, 256>>>(l1W, l1b, l2W, l2b, (float*)d_out);
}

// round 10
// speedup vs baseline: 3.1005x; 1.5203x over previous
#include <cuda_runtime.h>
#include <math.h>
#include <float.h>

#define NMAX 2048
#define HID  256
#define KMAX (NMAX/2)
#define CAP  256

// ---------------- scratch (device globals) -----------------------------------
__device__ float g_A[NMAX*NMAX];
__device__ float g_maskf[NMAX*NMAX];
__device__ float g_scoreT[NMAX*NMAX];
__device__ float g_SpT[KMAX*NMAX];
__device__ float g_M2T[KMAX*NMAX];
__device__ float g_Ac[KMAX*KMAX];
__device__ float g_part[4*NMAX*HID];    // split-K partial buffer (2M floats)
__device__ float g_h[NMAX*HID];
__device__ float g_g[NMAX*HID];
__device__ float g_xw[NMAX*HID];
__device__ float g_y[NMAX*HID];
__device__ float g_S[NMAX*HID];
__device__ float g_mm[NMAX*HID];
__device__ float g_xq[NMAX*HID];
__device__ float g_xnew[NMAX*HID];
__device__ float g_u[NMAX];
__device__ float g_v[NMAX];
__device__ float g_dinv[NMAX];
__device__ float g_av[NMAX];
__device__ float g_bv[NMAX];
__device__ float g_cv[NMAX];
__device__ float g_fit[NMAX];
__device__ float g_fvals[KMAX];
__device__ int   g_perm[KMAX];
__device__ float g_ro[2*HID];
__device__ int   g_nzidx[NMAX*CAP];
__device__ int   g_nzcnt[NMAX];
__device__ float g_sval[NMAX*CAP];

// ---------------- tiled fp32 GEMM / masked-max with split-K -------------------
// OP=0: C += A@B chunk (or A@B^T if TB). OP=1: masked max.
// Each block handles K-range [blockIdx.z*Kc, (z+1)*Kc); writes to C + z*M*N.
// Requires: M%64==0, N%64==0, Kc%16==0.
template<bool TB, int OP>
__global__ void __launch_bounds__(256) k_gemm(
    const float* __restrict__ A, const float* __restrict__ B, float* __restrict__ C,
    int M, int N, int Kc, int lda, int ldb, int ldc)
{
    __shared__ float As[16][64];
    __shared__ float Bs[16][64];
    const int tid = threadIdx.x;
    const int tx = tid & 15, ty = tid >> 4;
    const int m0 = blockIdx.y * 64, n0 = blockIdx.x * 64;
    const int ar = tid >> 2;
    const int ak = (tid & 3) << 2;
    const int bk = tid >> 4;
    const int bn = (tid & 15) << 2;
    const int kstart = blockIdx.z * Kc;
    float* Cz = C + (size_t)blockIdx.z * M * N;

    float acc[4][4];
#pragma unroll
    for (int i = 0; i < 4; i++)
#pragma unroll
        for (int j = 0; j < 4; j++) acc[i][j] = OP ? -FLT_MAX : 0.f;

    for (int k0 = kstart; k0 < kstart + Kc; k0 += 16) {
        float4 av = *(const float4*)(A + (size_t)(m0 + ar) * lda + (k0 + ak));
        As[ak+0][ar] = av.x; As[ak+1][ar] = av.y; As[ak+2][ar] = av.z; As[ak+3][ar] = av.w;
        if (TB) {
            float4 bv = *(const float4*)(B + (size_t)(n0 + ar) * ldb + (k0 + ak));
            Bs[ak+0][ar] = bv.x; Bs[ak+1][ar] = bv.y; Bs[ak+2][ar] = bv.z; Bs[ak+3][ar] = bv.w;
        } else {
            float4 bv = *(const float4*)(B + (size_t)(k0 + bk) * ldb + (n0 + bn));
            *(float4*)&Bs[bk][bn] = bv;
        }
        __syncthreads();
#pragma unroll
        for (int kk = 0; kk < 16; kk++) {
            float4 a4 = *(const float4*)&As[kk][ty << 2];
            float4 b4 = *(const float4*)&Bs[kk][tx << 2];
            if (OP == 0) {
                acc[0][0] += a4.x * b4.x; acc[0][1] += a4.x * b4.y; acc[0][2] += a4.x * b4.z; acc[0][3] += a4.x * b4.w;
                acc[1][0] += a4.y * b4.x; acc[1][1] += a4.y * b4.y; acc[1][2] += a4.y * b4.z; acc[1][3] += a4.y * b4.w;
                acc[2][0] += a4.z * b4.x; acc[2][1] += a4.z * b4.y; acc[2][2] += a4.z * b4.z; acc[2][3] += a4.z * b4.w;
                acc[3][0] += a4.w * b4.x; acc[3][1] += a4.w * b4.y; acc[3][2] += a4.w * b4.z; acc[3][3] += a4.w * b4.w;
            } else {
                float am[4] = {a4.x, a4.y, a4.z, a4.w};
                float bm[4] = {b4.x, b4.y, b4.z, b4.w};
#pragma unroll
                for (int i = 0; i < 4; i++)
#pragma unroll
                    for (int j = 0; j < 4; j++)
                        acc[i][j] = (am[i] != 0.f) ? fmaxf(acc[i][j], bm[j]) : acc[i][j];
            }
        }
        __syncthreads();
    }
#pragma unroll
    for (int i = 0; i < 4; i++) {
        float4 r; r.x = acc[i][0]; r.y = acc[i][1]; r.z = acc[i][2]; r.w = acc[i][3];
        *(float4*)(Cz + (size_t)(m0 + (ty << 2) + i) * ldc + n0 + (tx << 2)) = r;
    }
}

// reduce S split partials (fixed order). OP=0 sum, OP=1 max.
template<int OP>
__global__ void k_red(const float* __restrict__ part, float* __restrict__ out, int MN, int S) {
    int i = blockIdx.x * 256 + threadIdx.x;
    if (i >= MN) return;
    float v = part[i];
    for (int s = 1; s < S; s++) {
        float w = part[(size_t)s * MN + i];
        v = OP ? fmaxf(v, w) : v + w;
    }
    out[i] = v;
}

// ---------------- level-0 sparse kernels --------------------------------------
__global__ void k_scatter(const int* __restrict__ ei, int ne, int n) {
    int e = blockIdx.x * blockDim.x + threadIdx.x;
    if (e < ne) g_A[(size_t)ei[e] * n + ei[ne + e]] = 1.0f;
}

__global__ void k_buildnz(int n) {
    int w = threadIdx.x >> 5, lane = threadIdx.x & 31;
    int j = blockIdx.x * 8 + w;
    if (j >= n) return;
    const float* row = g_A + (size_t)j * n;
    int* idx = g_nzidx + (size_t)j * CAP;
    int cnt = 0;
    for (int c0 = 0; c0 < n; c0 += 32) {
        int i = c0 + lane;
        bool p = (row[i] != 0.f) || (i == j);
        unsigned m = __ballot_sync(0xffffffffu, p);
        int pos = cnt + __popc(m & ((1u << lane) - 1u));
        if (p && pos < CAP) idx[pos] = i;
        cnt += __popc(m);
    }
    if (cnt > CAP) cnt = CAP;
    if (lane == 0) {
        g_nzcnt[j] = cnt;
        g_dinv[j] = 1.0f / sqrtf((float)cnt);
    }
}

__global__ void k_scale(int n) {
    int idx = blockIdx.x * blockDim.x + threadIdx.x;
    if (idx < n * HID) g_y[idx] = g_dinv[idx >> 8] * g_xw[idx];
}

__global__ void k_gcn_gather(const float* __restrict__ bias) {
    __shared__ int sidx[CAP];
    int j = blockIdx.x, c = threadIdx.x;
    int cnt = g_nzcnt[j];
    const int* idx = g_nzidx + (size_t)j * CAP;
    for (int t = c; t < cnt; t += 256) sidx[t] = idx[t];
    __syncthreads();
    float acc = 0.f;
#pragma unroll 4
    for (int t = 0; t < cnt; t++) acc += g_y[(size_t)sidx[t] * HID + c];
    g_g[(size_t)j * HID + c] = fmaxf(g_dinv[j] * acc + bias[c], 0.f);
}

__global__ void k_max_gather() {
    __shared__ int sidx[CAP];
    int j = blockIdx.x, c = threadIdx.x;
    int cnt = g_nzcnt[j];
    const int* idx = g_nzidx + (size_t)j * CAP;
    for (int t = c; t < cnt; t += 256) sidx[t] = idx[t];
    __syncthreads();
    float m = -FLT_MAX;
#pragma unroll 4
    for (int t = 0; t < cnt; t++) m = fmaxf(m, g_g[(size_t)sidx[t] * HID + c]);
    g_mm[(size_t)j * HID + c] = m;
}

__global__ void k_uv(const float* __restrict__ linb, const float* __restrict__ attw, int n) {
    int w = (blockIdx.x * blockDim.x + threadIdx.x) >> 5;
    int lane = threadIdx.x & 31;
    if (w >= n) return;
    float su = 0.f, sv = 0.f;
    const float* xq = g_xq + (size_t)w * HID;
    const float* gg = g_g + (size_t)w * HID;
    for (int c = lane; c < HID; c += 32) {
        su += (xq[c] + linb[c]) * attw[c];
        sv += gg[c] * attw[HID + c];
    }
    for (int o = 16; o; o >>= 1) {
        su += __shfl_down_sync(0xffffffffu, su, o);
        sv += __shfl_down_sync(0xffffffffu, sv, o);
    }
    if (lane == 0) { g_u[w] = su; g_v[w] = sv; }
}

__global__ void k_softmax_nz(const float* __restrict__ attb, int n) {
    int w = threadIdx.x >> 5, lane = threadIdx.x & 31;
    int j = blockIdx.x * 8 + w;
    if (j >= n) return;
    int cnt = g_nzcnt[j];
    const int* idx = g_nzidx + (size_t)j * CAP;
    float uj = g_u[j] + attb[0];
    float mx = -FLT_MAX;
    for (int t = lane; t < cnt; t += 32) {
        float r = g_v[idx[t]] + uj; r = (r >= 0.f) ? r : 0.2f * r;
        mx = fmaxf(mx, r);
    }
    for (int o = 16; o; o >>= 1) mx = fmaxf(mx, __shfl_xor_sync(0xffffffffu, mx, o));
    float sm = 0.f;
    for (int t = lane; t < cnt; t += 32) {
        float r = g_v[idx[t]] + uj; r = (r >= 0.f) ? r : 0.2f * r;
        sm += expf(r - mx);
    }
    for (int o = 16; o; o >>= 1) sm += __shfl_xor_sync(0xffffffffu, sm, o);
    float* sval = g_sval + (size_t)j * CAP;
    for (int t = lane; t < cnt; t += 32) {
        float r = g_v[idx[t]] + uj; r = (r >= 0.f) ? r : 0.2f * r;
        sval[t] = expf(r - mx) / sm;
    }
}

__global__ void k_wsum_gather() {
    __shared__ int sidx[CAP];
    __shared__ float sw[CAP];
    int j = blockIdx.x, c = threadIdx.x;
    int cnt = g_nzcnt[j];
    const int* idx = g_nzidx + (size_t)j * CAP;
    const float* sv = g_sval + (size_t)j * CAP;
    for (int t = c; t < cnt; t += 256) { sidx[t] = idx[t]; sw[t] = sv[t]; }
    __syncthreads();
    float acc = 0.f;
#pragma unroll 4
    for (int t = 0; t < cnt; t++) acc += sw[t] * g_g[(size_t)sidx[t] * HID + c];
    g_xnew[(size_t)j * HID + c] = acc;
}

__global__ void k_abc(const float* __restrict__ le1W, const float* __restrict__ le1b,
                      const float* __restrict__ le2W, const float* __restrict__ le3W,
                      const float* __restrict__ le3b, int n) {
    int w = (blockIdx.x * blockDim.x + threadIdx.x) >> 5;
    int lane = threadIdx.x & 31;
    if (w >= n) return;
    const float* xr = g_xnew + (size_t)w * HID;
    float sa = 0.f, sb = 0.f, sc = 0.f;
    for (int c = lane; c < HID; c += 32) {
        float xv = xr[c];
        sa += xv * le1W[c]; sb += xv * le2W[c]; sc += xv * le3W[c];
    }
    for (int o = 16; o; o >>= 1) {
        sa += __shfl_down_sync(0xffffffffu, sa, o);
        sb += __shfl_down_sync(0xffffffffu, sb, o);
        sc += __shfl_down_sync(0xffffffffu, sc, o);
    }
    if (lane == 0) { g_av[w] = sa + le1b[0]; g_bv[w] = sb; g_cv[w] = sc + le3b[0]; }
}

__global__ void k_fit_nz(int n) {
    int w = threadIdx.x >> 5, lane = threadIdx.x & 31;
    int j = blockIdx.x * 8 + w;
    if (j >= n) return;
    int cnt = g_nzcnt[j];
    const int* idx = g_nzidx + (size_t)j * CAP;
    float s = 0.f;
    for (int t = lane; t < cnt; t += 32) s += g_av[idx[t]];
    for (int o = 16; o; o >>= 1) s += __shfl_xor_sync(0xffffffffu, s, o);
    if (lane == 0) {
        float z = s - (float)cnt * g_bv[j] + g_cv[j];
        g_fit[j] = 1.0f / (1.0f + expf(-z));
    }
}

__global__ void k_spscatter(int k) {
    int q = blockIdx.x, t = threadIdx.x;
    int pj = g_perm[q];
    if (t < g_nzcnt[pj])
        g_SpT[(size_t)g_nzidx[(size_t)pj * CAP + t] * k + q] = g_sval[(size_t)pj * CAP + t];
}

__global__ void k_m2(int k) {
    __shared__ int sidx[CAP];
    int j = blockIdx.x, c = threadIdx.x;
    int cnt = g_nzcnt[j];
    const int* idx = g_nzidx + (size_t)j * CAP;
    for (int t = c; t < cnt; t += 256) sidx[t] = idx[t];
    __syncthreads();
    float4 acc = {0.f, 0.f, 0.f, 0.f};
#pragma unroll 2
    for (int t = 0; t < cnt; t++) {
        float4 v = ((const float4*)(g_SpT + (size_t)sidx[t] * k))[c];
        acc.x += v.x; acc.y += v.y; acc.z += v.z; acc.w += v.w;
    }
    ((float4*)(g_M2T + (size_t)j * k))[c] = acc;
}

__global__ void k_acg(int k) {
    __shared__ int sidx[CAP];
    __shared__ float sw[CAP];
    int p = blockIdx.x, c = threadIdx.x;
    int pp = g_perm[p];
    int cnt = g_nzcnt[pp];
    const int* idx = g_nzidx + (size_t)pp * CAP;
    const float* sv = g_sval + (size_t)pp * CAP;
    for (int t = c; t < cnt; t += 256) { sidx[t] = idx[t]; sw[t] = sv[t]; }
    __syncthreads();
    float4 acc = {0.f, 0.f, 0.f, 0.f};
#pragma unroll 2
    for (int t = 0; t < cnt; t++) {
        float w = sw[t];
        float4 v = ((const float4*)(g_M2T + (size_t)sidx[t] * k))[c];
        acc.x += w * v.x; acc.y += w * v.y; acc.z += w * v.z; acc.w += w * v.w;
    }
    ((float4*)(g_Ac + (size_t)p * k))[c] = acc;
}

// ---------------- dense-path kernels (levels >= 1) ---------------------------
__global__ void k_dinv(int n) {
    int j = blockIdx.x, tid = threadIdx.x;
    __shared__ float red[256];
    const float* row = g_A + (size_t)j * n;
    float s = 0.f;
    for (int i = tid; i < n; i += 256) s += row[i];
    red[tid] = s; __syncthreads();
    for (int o = 128; o; o >>= 1) { if (tid < o) red[tid] += red[tid + o]; __syncthreads(); }
    if (tid == 0) g_dinv[j] = 1.0f / sqrtf(red[0] + 1.0f);
}

__global__ void k_gcnepi(const float* __restrict__ bias, int n) {
    int idx = blockIdx.x * blockDim.x + threadIdx.x;
    if (idx < n * HID) {
        int row = idx >> 8, c = idx & 255;
        float val = g_dinv[row] * (g_S[idx] + g_y[idx]) + bias[c];
        g_g[idx] = fmaxf(val, 0.f);
    }
}

__global__ void k_maskf(int n) {
    int idx = blockIdx.x * blockDim.x + threadIdx.x;
    if (idx < n * n) {
        int i = idx / n, j = idx - i * n;
        g_maskf[idx] = (g_A[idx] != 0.f || i == j) ? 1.f : 0.f;
    }
}

__global__ void k_softmax(const float* __restrict__ attb, int n) {
    int j = blockIdx.x, tid = threadIdx.x;
    __shared__ float red[256];
    __shared__ float s_mx, s_sum;
    const float* mrow = g_maskf + (size_t)j * n;
    float uj = g_u[j] + attb[0];
    float mx = -FLT_MAX;
    for (int i = tid; i < n; i += 256) {
        if (mrow[i] != 0.f) {
            float r = g_v[i] + uj; r = (r >= 0.f) ? r : 0.2f * r;
            mx = fmaxf(mx, r);
        }
    }
    red[tid] = mx; __syncthreads();
    for (int o = 128; o; o >>= 1) { if (tid < o) red[tid] = fmaxf(red[tid], red[tid + o]); __syncthreads(); }
    if (tid == 0) s_mx = red[0];
    __syncthreads();
    float sm = 0.f;
    for (int i = tid; i < n; i += 256) {
        if (mrow[i] != 0.f) {
            float r = g_v[i] + uj; r = (r >= 0.f) ? r : 0.2f * r;
            sm += expf(r - s_mx);
        }
    }
    red[tid] = sm; __syncthreads();
    for (int o = 128; o; o >>= 1) { if (tid < o) red[tid] += red[tid + o]; __syncthreads(); }
    if (tid == 0) s_sum = red[0];
    __syncthreads();
    float* srow = g_scoreT + (size_t)j * n;
    for (int i = tid; i < n; i += 256) {
        float val = 0.f;
        if (mrow[i] != 0.f) {
            float r = g_v[i] + uj; r = (r >= 0.f) ? r : 0.2f * r;
            val = expf(r - s_mx) / s_sum;
        }
        srow[i] = val;
    }
}

__global__ void k_fit(int n) {
    int j = blockIdx.x, tid = threadIdx.x;
    __shared__ float rs[256], rc[256];
    const float* mrow = g_maskf + (size_t)j * n;
    float s = 0.f, cn = 0.f;
    for (int i = tid; i < n; i += 256) {
        float mf = mrow[i];
        s += mf * g_av[i]; cn += mf;
    }
    rs[tid] = s; rc[tid] = cn; __syncthreads();
    for (int o = 128; o; o >>= 1) {
        if (tid < o) { rs[tid] += rs[tid + o]; rc[tid] += rc[tid + o]; }
        __syncthreads();
    }
    if (tid == 0) {
        float z = rs[0] - rc[0] * g_bv[j] + g_cv[j];
        g_fit[j] = 1.0f / (1.0f + expf(-z));
    }
}

__global__ void k_sort(int n, int k) {
    __shared__ float sv[NMAX];
    __shared__ int   si[NMAX];
    int tid = threadIdx.x;
    for (int i = tid; i < n; i += blockDim.x) { sv[i] = g_fit[i]; si[i] = i; }
    __syncthreads();
    for (int size = 2; size <= n; size <<= 1) {
        for (int stride = size >> 1; stride > 0; stride >>= 1) {
            for (int i = tid; i < n; i += blockDim.x) {
                int j = i ^ stride;
                if (j > i) {
                    bool descBlk = ((i & size) == 0);
                    float va = sv[i], vb = sv[j];
                    int ia = si[i], ib = si[j];
                    bool before = (va > vb) || (va == vb && ia < ib);
                    bool dosw = descBlk ? (!before) : before;
                    if (dosw) { sv[i] = vb; sv[j] = va; si[i] = ib; si[j] = ia; }
                }
            }
            __syncthreads();
        }
    }
    for (int t = tid; t < k; t += blockDim.x) { g_perm[t] = si[t]; g_fvals[t] = sv[t]; }
}

__global__ void k_pool(int k) {
    int q = blockIdx.x, c = threadIdx.x;
    g_h[(size_t)q * HID + c] = g_xnew[(size_t)g_perm[q] * HID + c] * g_fvals[q];
}

// one block per column c: sum+max over k rows
__global__ void k_readout(int k) {
    __shared__ float rs[256], rm[256];
    int c = blockIdx.x, tid = threadIdx.x;
    float s = 0.f, m = -FLT_MAX;
    for (int q = tid; q < k; q += 256) {
        float v = g_h[(size_t)q * HID + c];
        s += v; m = fmaxf(m, v);
    }
    rs[tid] = s; rm[tid] = m; __syncthreads();
    for (int o = 128; o; o >>= 1) {
        if (tid < o) { rs[tid] += rs[tid + o]; rm[tid] = fmaxf(rm[tid], rm[tid + o]); }
        __syncthreads();
    }
    if (tid == 0) {
        g_ro[c] += rs[0] / (float)k;
        g_ro[HID + c] += rm[0];
    }
}

__global__ void k_gatherSpT(int n, int k) {
    int i = blockIdx.x * 256 + threadIdx.x;
    int q = blockIdx.y;
    g_SpT[(size_t)q * n + i] = g_scoreT[(size_t)g_perm[q] * n + i];
}

__global__ void k_setA(int k) {
    int idx = blockIdx.x * blockDim.x + threadIdx.x;
    if (idx < k * k) {
        int p = idx / k, q = idx - p * k;
        g_A[idx] = (p == q) ? 0.f : g_Ac[idx];
    }
}

__global__ void k_head(const float* __restrict__ l1W, const float* __restrict__ l1b,
                       const float* __restrict__ l2W, const float* __restrict__ l2b,
                       float* __restrict__ out) {
    __shared__ float hid[HID];
    __shared__ float lg[16];
    int t = threadIdx.x;
    float s = l1b[t];
    for (int kk = 0; kk < 2 * HID; kk++) s += g_ro[kk] * l1W[kk * HID + t];
    hid[t] = fmaxf(s, 0.f);
    __syncthreads();
    if (t < 10) {
        float s2 = l2b[t];
        for (int c = 0; c < HID; c++) s2 += hid[c] * l2W[c * 10 + t];
        lg[t] = s2;
    }
    __syncthreads();
    if (t == 0) {
        float m = lg[0];
        for (int i = 1; i < 10; i++) m = fmaxf(m, lg[i]);
        float sm = 0.f;
        for (int i = 0; i < 10; i++) sm += expf(lg[i] - m);
        float ls = logf(sm);
        for (int i = 0; i < 10; i++) out[i] = lg[i] - m - ls;
    }
}

// ---------------- launcher ---------------------------------------------------
extern "C" void kernel_launch(void* const* d_in, const int* in_sizes, int n_in,
                              void* d_out, int out_size) {
    const float* x    = (const float*)d_in[0];
    const int*   ei   = (const int*)d_in[1];
    const float* W1   = (const float*)d_in[2];
    const float* b1   = (const float*)d_in[3];
    const float* W2   = (const float*)d_in[4];
    const float* b2   = (const float*)d_in[5];
    const float* linW = (const float*)d_in[6];
    const float* linb = (const float*)d_in[7];
    const float* attw = (const float*)d_in[8];
    const float* attb = (const float*)d_in[9];
    const float* le1W = (const float*)d_in[10];
    const float* le1b = (const float*)d_in[11];
    const float* le2W = (const float*)d_in[12];
    const float* le3W = (const float*)d_in[13];
    const float* le3b = (const float*)d_in[14];
    const float* l1W  = (const float*)d_in[15];
    const float* l1b  = (const float*)d_in[16];
    const float* l2W  = (const float*)d_in[17];
    const float* l2b  = (const float*)d_in[18];

    float *pA, *pmask, *pscoreT, *pSpT, *pM2T, *pAc, *pPart;
    float *pxw, *py, *pS, *pmm, *pxq, *pxnew, *ph, *pg, *pro;
    cudaGetSymbolAddress((void**)&pA, g_A);
    cudaGetSymbolAddress((void**)&pmask, g_maskf);
    cudaGetSymbolAddress((void**)&pscoreT, g_scoreT);
    cudaGetSymbolAddress((void**)&pSpT, g_SpT);
    cudaGetSymbolAddress((void**)&pM2T, g_M2T);
    cudaGetSymbolAddress((void**)&pAc, g_Ac);
    cudaGetSymbolAddress((void**)&pPart, g_part);
    cudaGetSymbolAddress((void**)&pxw, g_xw);
    cudaGetSymbolAddress((void**)&py, g_y);
    cudaGetSymbolAddress((void**)&pS, g_S);
    cudaGetSymbolAddress((void**)&pmm, g_mm);
    cudaGetSymbolAddress((void**)&pxq, g_xq);
    cudaGetSymbolAddress((void**)&pxnew, g_xnew);
    cudaGetSymbolAddress((void**)&ph, g_h);
    cudaGetSymbolAddress((void**)&pg, g_g);
    cudaGetSymbolAddress((void**)&pro, g_ro);

    int n = 2048;
    int ne = in_sizes[1] / 2;

    cudaMemsetAsync(pA, 0, (size_t)n * n * sizeof(float));
    cudaMemsetAsync(pro, 0, 2 * HID * sizeof(float));
    k_scatter<<<(ne + 255) / 256, 256>>>(ei, ne, n);

    const float* X = x;
    int f_in = 128;

    for (int lvl = 0; lvl < 3; lvl++) {
        const float* W  = lvl ? W2 : W1;
        const float* bb = lvl ? b2 : b1;
        int k = n / 2;
        int nh = n * HID;
        int rg = (nh + 255) / 256;

        if (lvl == 0) {
            // ---- sparse level-0 path ----
            // xw = X@W1 (K=128, split 2)
            k_gemm<false,0><<<dim3(HID/64, n/64, 2), 256>>>(X, W, pPart, n, HID, f_in/2, f_in, HID, HID);
            k_red<0><<<rg, 256>>>(pPart, pxw, nh, 2);
            k_buildnz<<<n / 8, 256>>>(n);
            k_scale<<<rg, 256>>>(n);
            k_gcn_gather<<<n, 256>>>(bb);
            k_max_gather<<<n, 256>>>();
            // xq = mm@linW (K=256, split 2)
            k_gemm<false,0><<<dim3(HID/64, n/64, 2), 256>>>(pmm, linW, pPart, n, HID, HID/2, HID, HID, HID);
            k_red<0><<<rg, 256>>>(pPart, pxq, nh, 2);
            k_uv<<<(n * 32 + 255) / 256, 256>>>(linb, attw, n);
            k_softmax_nz<<<n / 8, 256>>>(attb, n);
            k_wsum_gather<<<n, 256>>>();
            k_abc<<<(n * 32 + 255) / 256, 256>>>(le1W, le1b, le2W, le3W, le3b, n);
            k_fit_nz<<<n / 8, 256>>>(n);
            k_sort<<<1, 1024>>>(n, k);
            k_pool<<<k, 256>>>(k);
            k_readout<<<HID, 256>>>(k);
            cudaMemsetAsync(pSpT, 0, (size_t)n * k * sizeof(float));
            k_spscatter<<<k, 256>>>(k);
            k_m2<<<n, 256>>>(k);
            k_acg<<<k, 256>>>(k);
            k_setA<<<(k * k + 255) / 256, 256>>>(k);
        } else {
            // ---- dense path ----
            int S = (n == 1024) ? 4 : 8;   // split-K factor for feature GEMMs
            dim3 gS(HID/64, n/64, S);

            // xw = X@W (K=256)
            k_gemm<false,0><<<gS, 256>>>(X, W, pPart, n, HID, HID/S, HID, HID, HID);
            k_red<0><<<rg, 256>>>(pPart, pxw, nh, S);
            k_dinv<<<n, 256>>>(n);
            k_scale<<<rg, 256>>>(n);
            // S = A@y (K=n)
            k_gemm<false,0><<<gS, 256>>>(pA, py, pPart, n, HID, n/S, n, HID, HID);
            k_red<0><<<rg, 256>>>(pPart, pS, nh, S);
            k_gcnepi<<<rg, 256>>>(bb, n);

            k_maskf<<<(n * n + 255) / 256, 256>>>(n);
            // mm = maskedmax(mask, g) (K=n)
            k_gemm<false,1><<<gS, 256>>>(pmask, pg, pPart, n, HID, n/S, n, HID, HID);
            k_red<1><<<rg, 256>>>(pPart, pmm, nh, S);
            // xq = mm@linW (K=256)
            k_gemm<false,0><<<gS, 256>>>(pmm, linW, pPart, n, HID, HID/S, HID, HID, HID);
            k_red<0><<<rg, 256>>>(pPart, pxq, nh, S);
            k_uv<<<(n * 32 + 255) / 256, 256>>>(linb, attw, n);
            k_softmax<<<n, 256>>>(attb, n);
            // xnew = scoreT@g (K=n)
            k_gemm<false,0><<<gS, 256>>>(pscoreT, pg, pPart, n, HID, n/S, n, HID, HID);
            k_red<0><<<rg, 256>>>(pPart, pxnew, nh, S);

            k_abc<<<(n * 32 + 255) / 256, 256>>>(le1W, le1b, le2W, le3W, le3b, n);
            k_fit<<<n, 256>>>(n);
            k_sort<<<1, 1024>>>(n, k);
            k_pool<<<k, 256>>>(k);
            k_readout<<<HID, 256>>>(k);

            if (lvl < 2) {
                k_gatherSpT<<<dim3(n / 256, k), 256>>>(n, k);
                // M2T = SpT@mask (M=k, N=n, K=n, split 2)
                k_gemm<false,0><<<dim3(n/64, k/64, 2), 256>>>(pSpT, pmask, pPart, k, n, n/2, n, n, n);
                k_red<0><<<(k * n + 255) / 256, 256>>>(pPart, pM2T, k * n, 2);
                // Ac = SpT@M2T^T (M=k, N=k, K=n, split 4)
                k_gemm<true,0><<<dim3(k/64, k/64, 4), 256>>>(pSpT, pM2T, pPart, k, k, n/4, n, n, k);
                k_red<0><<<(k * k + 255) / 256, 256>>>(pPart, pAc, k * k, 4);
                k_setA<<<(k * k + 255) / 256, 256>>>(k);
            }
        }

        X = ph; f_in = HID; n = k;
    }

    k_head<<<1, 256>>>(l1W, l1b, l2W, l2b, (float*)d_out);
}

// round 13
// speedup vs baseline: 3.2907x; 1.0614x over previous
#include <cuda_runtime.h>
#include <math.h>
#include <float.h>

#define NMAX 2048
#define HID  256
#define KMAX (NMAX/2)
#define CAP  256

// ---------------- scratch (device globals) -----------------------------------
// g_A stores A1 = A + I at every level (diag forced to 1).
__device__ float g_A[NMAX*NMAX];
__device__ float g_scoreT[NMAX*NMAX];
__device__ float g_SpT[KMAX*NMAX];
__device__ float g_M2T[KMAX*NMAX];
__device__ float g_Ac[KMAX*KMAX];
__device__ float g_part[4*NMAX*HID];    // split-K partial buffer
__device__ float g_h[NMAX*HID];
__device__ float g_g[NMAX*HID];
__device__ float g_y[NMAX*HID];
__device__ float g_mm[NMAX*HID];
__device__ float g_xq[NMAX*HID];
__device__ float g_xnew[NMAX*HID];
__device__ float g_u[NMAX];
__device__ float g_v[NMAX];
__device__ float g_dinv[NMAX];
__device__ float g_av[NMAX];
__device__ float g_bv[NMAX];
__device__ float g_cv[NMAX];
__device__ float g_fit[NMAX];
__device__ float g_fvals[KMAX];
__device__ int   g_perm[KMAX];
__device__ float g_ro[2*HID];
__device__ int   g_nzidx[NMAX*CAP];
__device__ int   g_nzcnt[NMAX];
__device__ float g_sval[NMAX*CAP];

// ---------------- tiled fp32 GEMM with split-K --------------------------------
// OP=0: C = A@B chunk (A@B^T if TB). OP=1: masked max (A entry !=0 gates B).
// OP=2: C = A@binarize(B) chunk (B entries mapped to 0/1 at load).
// Block handles K-range [z*Kc,(z+1)*Kc), writes partial to C + z*M*N.
template<bool TB, int OP>
__global__ void __launch_bounds__(256) k_gemm(
    const float* __restrict__ A, const float* __restrict__ B, float* __restrict__ C,
    int M, int N, int Kc, int lda, int ldb, int ldc)
{
    __shared__ float As[16][64];
    __shared__ float Bs[16][64];
    const int tid = threadIdx.x;
    const int tx = tid & 15, ty = tid >> 4;
    const int m0 = blockIdx.y * 64, n0 = blockIdx.x * 64;
    const int ar = tid >> 2;
    const int ak = (tid & 3) << 2;
    const int bk = tid >> 4;
    const int bn = (tid & 15) << 2;
    const int kstart = blockIdx.z * Kc;
    float* Cz = C + (size_t)blockIdx.z * M * N;

    float acc[4][4];
#pragma unroll
    for (int i = 0; i < 4; i++)
#pragma unroll
        for (int j = 0; j < 4; j++) acc[i][j] = (OP == 1) ? -FLT_MAX : 0.f;

    for (int k0 = kstart; k0 < kstart + Kc; k0 += 16) {
        float4 av = *(const float4*)(A + (size_t)(m0 + ar) * lda + (k0 + ak));
        As[ak+0][ar] = av.x; As[ak+1][ar] = av.y; As[ak+2][ar] = av.z; As[ak+3][ar] = av.w;
        if (TB) {
            float4 bv = *(const float4*)(B + (size_t)(n0 + ar) * ldb + (k0 + ak));
            Bs[ak+0][ar] = bv.x; Bs[ak+1][ar] = bv.y; Bs[ak+2][ar] = bv.z; Bs[ak+3][ar] = bv.w;
        } else {
            float4 bv = *(const float4*)(B + (size_t)(k0 + bk) * ldb + (n0 + bn));
            if (OP == 2) {
                bv.x = (bv.x != 0.f) ? 1.f : 0.f;
                bv.y = (bv.y != 0.f) ? 1.f : 0.f;
                bv.z = (bv.z != 0.f) ? 1.f : 0.f;
                bv.w = (bv.w != 0.f) ? 1.f : 0.f;
            }
            *(float4*)&Bs[bk][bn] = bv;
        }
        __syncthreads();
#pragma unroll
        for (int kk = 0; kk < 16; kk++) {
            float4 a4 = *(const float4*)&As[kk][ty << 2];
            float4 b4 = *(const float4*)&Bs[kk][tx << 2];
            if (OP != 1) {
                acc[0][0] += a4.x * b4.x; acc[0][1] += a4.x * b4.y; acc[0][2] += a4.x * b4.z; acc[0][3] += a4.x * b4.w;
                acc[1][0] += a4.y * b4.x; acc[1][1] += a4.y * b4.y; acc[1][2] += a4.y * b4.z; acc[1][3] += a4.y * b4.w;
                acc[2][0] += a4.z * b4.x; acc[2][1] += a4.z * b4.y; acc[2][2] += a4.z * b4.z; acc[2][3] += a4.z * b4.w;
                acc[3][0] += a4.w * b4.x; acc[3][1] += a4.w * b4.y; acc[3][2] += a4.w * b4.z; acc[3][3] += a4.w * b4.w;
            } else {
                float am[4] = {a4.x, a4.y, a4.z, a4.w};
                float bm[4] = {b4.x, b4.y, b4.z, b4.w};
#pragma unroll
                for (int i = 0; i < 4; i++)
#pragma unroll
                    for (int j = 0; j < 4; j++)
                        acc[i][j] = (am[i] != 0.f) ? fmaxf(acc[i][j], bm[j]) : acc[i][j];
            }
        }
        __syncthreads();
    }
#pragma unroll
    for (int i = 0; i < 4; i++) {
        float4 r; r.x = acc[i][0]; r.y = acc[i][1]; r.z = acc[i][2]; r.w = acc[i][3];
        *(float4*)(Cz + (size_t)(m0 + (ty << 2) + i) * ldc + n0 + (tx << 2)) = r;
    }
}

// reduce S split partials (fixed order). OP=0 sum, OP=1 max.
template<int OP>
__global__ void k_red(const float* __restrict__ part, float* __restrict__ out, int MN, int S) {
    int i = blockIdx.x * 256 + threadIdx.x;
    if (i >= MN) return;
    float v = part[i];
    for (int s = 1; s < S; s++) {
        float w = part[(size_t)s * MN + i];
        v = OP ? fmaxf(v, w) : v + w;
    }
    out[i] = v;
}

// sum partials then scale by dinv[row]: y = dinv * (X@W)
__global__ void k_redscale(const float* __restrict__ part, float* __restrict__ out, int MN, int S) {
    int i = blockIdx.x * 256 + threadIdx.x;
    if (i >= MN) return;
    float v = part[i];
    for (int s = 1; s < S; s++) v += part[(size_t)s * MN + i];
    out[i] = g_dinv[i >> 8] * v;
}

// sum partials of A1@y then GCN epilogue: g = relu(dinv*sum + bias)
__global__ void k_redgcn(const float* __restrict__ part, const float* __restrict__ bias,
                         float* __restrict__ out, int MN, int S) {
    int i = blockIdx.x * 256 + threadIdx.x;
    if (i >= MN) return;
    float v = part[i];
    for (int s = 1; s < S; s++) v += part[(size_t)s * MN + i];
    out[i] = fmaxf(g_dinv[i >> 8] * v + bias[i & 255], 0.f);
}

// ---------------- level-0 sparse kernels --------------------------------------
__global__ void k_scatter(const int* __restrict__ ei, int ne, int n) {
    int e = blockIdx.x * blockDim.x + threadIdx.x;
    if (e < ne) g_A[(size_t)ei[e] * n + ei[ne + e]] = 1.0f;
}

__global__ void k_diag(int n) {
    int i = blockIdx.x * 256 + threadIdx.x;
    if (i < n) g_A[(size_t)i * n + i] = 1.0f;
}

// block per row: compact nonzero indices of A1 row (ascending, deterministic)
__global__ void k_buildnz(int n) {
    __shared__ int sc[256];
    int j = blockIdx.x, t = threadIdx.x;
    const float* row = g_A + (size_t)j * n;
    int seg = n >> 8;             // 8 for n=2048
    int base = t * seg;
    float vals[8];
    int cnt = 0;
#pragma unroll
    for (int i = 0; i < 8; i++) {
        float v = (i < seg) ? row[base + i] : 0.f;
        vals[i] = v;
        cnt += (v != 0.f);
    }
    sc[t] = cnt;
    __syncthreads();
    for (int o = 1; o < 256; o <<= 1) {
        int x = (t >= o) ? sc[t - o] : 0;
        __syncthreads();
        sc[t] += x;
        __syncthreads();
    }
    int pos = sc[t] - cnt;        // exclusive prefix
    int total = sc[255];
    int* idx = g_nzidx + (size_t)j * CAP;
#pragma unroll
    for (int i = 0; i < 8; i++) {
        if (vals[i] != 0.f) {
            if (pos < CAP) idx[pos] = base + i;
            pos++;
        }
    }
    if (t == 0) {
        g_nzcnt[j] = (total > CAP) ? CAP : total;
        g_dinv[j] = 1.0f / sqrtf((float)total);   // deg = row count of A1 (all ones)
    }
}

__global__ void k_gcn_gather(const float* __restrict__ bias) {
    __shared__ int sidx[CAP];
    int j = blockIdx.x, c = threadIdx.x;
    int cnt = g_nzcnt[j];
    const int* idx = g_nzidx + (size_t)j * CAP;
    for (int t = c; t < cnt; t += 256) sidx[t] = idx[t];
    __syncthreads();
    float acc = 0.f;
#pragma unroll 4
    for (int t = 0; t < cnt; t++) acc += g_y[(size_t)sidx[t] * HID + c];
    g_g[(size_t)j * HID + c] = fmaxf(g_dinv[j] * acc + bias[c], 0.f);
}

__global__ void k_max_gather() {
    __shared__ int sidx[CAP];
    int j = blockIdx.x, c = threadIdx.x;
    int cnt = g_nzcnt[j];
    const int* idx = g_nzidx + (size_t)j * CAP;
    for (int t = c; t < cnt; t += 256) sidx[t] = idx[t];
    __syncthreads();
    float m = -FLT_MAX;
#pragma unroll 4
    for (int t = 0; t < cnt; t++) m = fmaxf(m, g_g[(size_t)sidx[t] * HID + c]);
    g_mm[(size_t)j * HID + c] = m;
}

__global__ void k_uv(const float* __restrict__ linb, const float* __restrict__ attw, int n) {
    int w = (blockIdx.x * blockDim.x + threadIdx.x) >> 5;
    int lane = threadIdx.x & 31;
    if (w >= n) return;
    float su = 0.f, sv = 0.f;
    const float* xq = g_xq + (size_t)w * HID;
    const float* gg = g_g + (size_t)w * HID;
    for (int c = lane; c < HID; c += 32) {
        su += (xq[c] + linb[c]) * attw[c];
        sv += gg[c] * attw[HID + c];
    }
    for (int o = 16; o; o >>= 1) {
        su += __shfl_down_sync(0xffffffffu, su, o);
        sv += __shfl_down_sync(0xffffffffu, sv, o);
    }
    if (lane == 0) { g_u[w] = su; g_v[w] = sv; }
}

__global__ void k_softmax_nz(const float* __restrict__ attb, int n) {
    int w = threadIdx.x >> 5, lane = threadIdx.x & 31;
    int j = blockIdx.x * 8 + w;
    if (j >= n) return;
    int cnt = g_nzcnt[j];
    const int* idx = g_nzidx + (size_t)j * CAP;
    float uj = g_u[j] + attb[0];
    float mx = -FLT_MAX;
    for (int t = lane; t < cnt; t += 32) {
        float r = g_v[idx[t]] + uj; r = (r >= 0.f) ? r : 0.2f * r;
        mx = fmaxf(mx, r);
    }
    for (int o = 16; o; o >>= 1) mx = fmaxf(mx, __shfl_xor_sync(0xffffffffu, mx, o));
    float sm = 0.f;
    for (int t = lane; t < cnt; t += 32) {
        float r = g_v[idx[t]] + uj; r = (r >= 0.f) ? r : 0.2f * r;
        sm += expf(r - mx);
    }
    for (int o = 16; o; o >>= 1) sm += __shfl_xor_sync(0xffffffffu, sm, o);
    float* sval = g_sval + (size_t)j * CAP;
    for (int t = lane; t < cnt; t += 32) {
        float r = g_v[idx[t]] + uj; r = (r >= 0.f) ? r : 0.2f * r;
        sval[t] = expf(r - mx) / sm;
    }
}

__global__ void k_wsum_gather() {
    __shared__ int sidx[CAP];
    __shared__ float sw[CAP];
    int j = blockIdx.x, c = threadIdx.x;
    int cnt = g_nzcnt[j];
    const int* idx = g_nzidx + (size_t)j * CAP;
    const float* sv = g_sval + (size_t)j * CAP;
    for (int t = c; t < cnt; t += 256) { sidx[t] = idx[t]; sw[t] = sv[t]; }
    __syncthreads();
    float acc = 0.f;
#pragma unroll 4
    for (int t = 0; t < cnt; t++) acc += sw[t] * g_g[(size_t)sidx[t] * HID + c];
    g_xnew[(size_t)j * HID + c] = acc;
}

__global__ void k_abc(const float* __restrict__ le1W, const float* __restrict__ le1b,
                      const float* __restrict__ le2W, const float* __restrict__ le3W,
                      const float* __restrict__ le3b, int n) {
    int w = (blockIdx.x * blockDim.x + threadIdx.x) >> 5;
    int lane = threadIdx.x & 31;
    if (w >= n) return;
    const float* xr = g_xnew + (size_t)w * HID;
    float sa = 0.f, sb = 0.f, sc = 0.f;
    for (int c = lane; c < HID; c += 32) {
        float xv = xr[c];
        sa += xv * le1W[c]; sb += xv * le2W[c]; sc += xv * le3W[c];
    }
    for (int o = 16; o; o >>= 1) {
        sa += __shfl_down_sync(0xffffffffu, sa, o);
        sb += __shfl_down_sync(0xffffffffu, sb, o);
        sc += __shfl_down_sync(0xffffffffu, sc, o);
    }
    if (lane == 0) { g_av[w] = sa + le1b[0]; g_bv[w] = sb; g_cv[w] = sc + le3b[0]; }
}

__global__ void k_fit_nz(int n) {
    int w = threadIdx.x >> 5, lane = threadIdx.x & 31;
    int j = blockIdx.x * 8 + w;
    if (j >= n) return;
    int cnt = g_nzcnt[j];
    const int* idx = g_nzidx + (size_t)j * CAP;
    float s = 0.f;
    for (int t = lane; t < cnt; t += 32) s += g_av[idx[t]];
    for (int o = 16; o; o >>= 1) s += __shfl_xor_sync(0xffffffffu, s, o);
    if (lane == 0) {
        float z = s - (float)cnt * g_bv[j] + g_cv[j];
        g_fit[j] = 1.0f / (1.0f + expf(-z));
    }
}

__global__ void k_spscatter(int k) {
    int q = blockIdx.x, t = threadIdx.x;
    int pj = g_perm[q];
    if (t < g_nzcnt[pj])
        g_SpT[(size_t)g_nzidx[(size_t)pj * CAP + t] * k + q] = g_sval[(size_t)pj * CAP + t];
}

__global__ void k_m2(int k) {
    __shared__ int sidx[CAP];
    int j = blockIdx.x, c = threadIdx.x;
    int cnt = g_nzcnt[j];
    const int* idx = g_nzidx + (size_t)j * CAP;
    for (int t = c; t < cnt; t += 256) sidx[t] = idx[t];
    __syncthreads();
    float4 acc = {0.f, 0.f, 0.f, 0.f};
#pragma unroll 2
    for (int t = 0; t < cnt; t++) {
        float4 v = ((const float4*)(g_SpT + (size_t)sidx[t] * k))[c];
        acc.x += v.x; acc.y += v.y; acc.z += v.z; acc.w += v.w;
    }
    ((float4*)(g_M2T + (size_t)j * k))[c] = acc;
}

__global__ void k_acg(int k) {
    __shared__ int sidx[CAP];
    __shared__ float sw[CAP];
    int p = blockIdx.x, c = threadIdx.x;
    int pp = g_perm[p];
    int cnt = g_nzcnt[pp];
    const int* idx = g_nzidx + (size_t)pp * CAP;
    const float* sv = g_sval + (size_t)pp * CAP;
    for (int t = c; t < cnt; t += 256) { sidx[t] = idx[t]; sw[t] = sv[t]; }
    __syncthreads();
    float4 acc = {0.f, 0.f, 0.f, 0.f};
#pragma unroll 2
    for (int t = 0; t < cnt; t++) {
        float w = sw[t];
        float4 v = ((const float4*)(g_M2T + (size_t)sidx[t] * k))[c];
        acc.x += w * v.x; acc.y += w * v.y; acc.z += w * v.z; acc.w += w * v.w;
    }
    ((float4*)(g_Ac + (size_t)p * k))[c] = acc;
}

// ---------------- dense-path kernels (levels >= 1; g_A holds A1) --------------
__global__ void k_dinv(int n) {
    int j = blockIdx.x, tid = threadIdx.x;
    __shared__ float red[256];
    const float* row = g_A + (size_t)j * n;
    float s = 0.f;
    for (int i = tid; i < n; i += 256) s += row[i];
    red[tid] = s; __syncthreads();
    for (int o = 128; o; o >>= 1) { if (tid < o) red[tid] += red[tid + o]; __syncthreads(); }
    if (tid == 0) g_dinv[j] = 1.0f / sqrtf(red[0]);
}

__global__ void k_softmax(const float* __restrict__ attb, int n) {
    int j = blockIdx.x, tid = threadIdx.x;
    __shared__ float red[256];
    __shared__ float s_mx, s_sum;
    const float* mrow = g_A + (size_t)j * n;   // A1: nonzero = masked
    float uj = g_u[j] + attb[0];
    float mx = -FLT_MAX;
    for (int i = tid; i < n; i += 256) {
        if (mrow[i] != 0.f) {
            float r = g_v[i] + uj; r = (r >= 0.f) ? r : 0.2f * r;
            mx = fmaxf(mx, r);
        }
    }
    red[tid] = mx; __syncthreads();
    for (int o = 128; o; o >>= 1) { if (tid < o) red[tid] = fmaxf(red[tid], red[tid + o]); __syncthreads(); }
    if (tid == 0) s_mx = red[0];
    __syncthreads();
    float sm = 0.f;
    for (int i = tid; i < n; i += 256) {
        if (mrow[i] != 0.f) {
            float r = g_v[i] + uj; r = (r >= 0.f) ? r : 0.2f * r;
            sm += expf(r - s_mx);
        }
    }
    red[tid] = sm; __syncthreads();
    for (int o = 128; o; o >>= 1) { if (tid < o) red[tid] += red[tid + o]; __syncthreads(); }
    if (tid == 0) s_sum = red[0];
    __syncthreads();
    float* srow = g_scoreT + (size_t)j * n;
    for (int i = tid; i < n; i += 256) {
        float val = 0.f;
        if (mrow[i] != 0.f) {
            float r = g_v[i] + uj; r = (r >= 0.f) ? r : 0.2f * r;
            val = expf(r - s_mx) / s_sum;
        }
        srow[i] = val;
    }
}

__global__ void k_fit(int n) {
    int j = blockIdx.x, tid = threadIdx.x;
    __shared__ float rs[256], rc[256];
    const float* mrow = g_A + (size_t)j * n;
    float s = 0.f, cn = 0.f;
    for (int i = tid; i < n; i += 256) {
        if (mrow[i] != 0.f) { s += g_av[i]; cn += 1.f; }
    }
    rs[tid] = s; rc[tid] = cn; __syncthreads();
    for (int o = 128; o; o >>= 1) {
        if (tid < o) { rs[tid] += rs[tid + o]; rc[tid] += rc[tid + o]; }
        __syncthreads();
    }
    if (tid == 0) {
        float z = rs[0] - rc[0] * g_bv[j] + g_cv[j];
        g_fit[j] = 1.0f / (1.0f + expf(-z));
    }
}

__global__ void k_sort(int n, int k) {
    __shared__ float sv[NMAX];
    __shared__ int   si[NMAX];
    int tid = threadIdx.x;
    for (int i = tid; i < n; i += blockDim.x) { sv[i] = g_fit[i]; si[i] = i; }
    __syncthreads();
    for (int size = 2; size <= n; size <<= 1) {
        for (int stride = size >> 1; stride > 0; stride >>= 1) {
            for (int i = tid; i < n; i += blockDim.x) {
                int j = i ^ stride;
                if (j > i) {
                    bool descBlk = ((i & size) == 0);
                    float va = sv[i], vb = sv[j];
                    int ia = si[i], ib = si[j];
                    bool before = (va > vb) || (va == vb && ia < ib);
                    bool dosw = descBlk ? (!before) : before;
                    if (dosw) { sv[i] = vb; sv[j] = va; si[i] = ib; si[j] = ia; }
                }
            }
            __syncthreads();
        }
    }
    for (int t = tid; t < k; t += blockDim.x) { g_perm[t] = si[t]; g_fvals[t] = sv[t]; }
}

__global__ void k_pool(int k) {
    int q = blockIdx.x, c = threadIdx.x;
    g_h[(size_t)q * HID + c] = g_xnew[(size_t)g_perm[q] * HID + c] * g_fvals[q];
}

__global__ void k_readout(int k) {
    __shared__ float rs[256], rm[256];
    int c = blockIdx.x, tid = threadIdx.x;
    float s = 0.f, m = -FLT_MAX;
    for (int q = tid; q < k; q += 256) {
        float v = g_h[(size_t)q * HID + c];
        s += v; m = fmaxf(m, v);
    }
    rs[tid] = s; rm[tid] = m; __syncthreads();
    for (int o = 128; o; o >>= 1) {
        if (tid < o) { rs[tid] += rs[tid + o]; rm[tid] = fmaxf(rm[tid], rm[tid + o]); }
        __syncthreads();
    }
    if (tid == 0) {
        g_ro[c] += rs[0] / (float)k;
        g_ro[HID + c] += rm[0];
    }
}

__global__ void k_gatherSpT(int n, int k) {
    int i = blockIdx.x * 256 + threadIdx.x;
    int q = blockIdx.y;
    g_SpT[(size_t)q * n + i] = g_scoreT[(size_t)g_perm[q] * n + i];
}

// A <- A1 of coarsened graph: off-diag from Ac, diag = 1
__global__ void k_setA(int k) {
    int idx = blockIdx.x * blockDim.x + threadIdx.x;
    if (idx < k * k) {
        int p = idx / k, q = idx - p * k;
        g_A[idx] = (p == q) ? 1.f : g_Ac[idx];
    }
}

__global__ void k_head(const float* __restrict__ l1W, const float* __restrict__ l1b,
                       const float* __restrict__ l2W, const float* __restrict__ l2b,
                       float* __restrict__ out) {
    __shared__ float hid[HID];
    __shared__ float lg[16];
    int t = threadIdx.x;
    float s = l1b[t];
    for (int kk = 0; kk < 2 * HID; kk++) s += g_ro[kk] * l1W[kk * HID + t];
    hid[t] = fmaxf(s, 0.f);
    __syncthreads();
    if (t < 10) {
        float s2 = l2b[t];
        for (int c = 0; c < HID; c++) s2 += hid[c] * l2W[c * 10 + t];
        lg[t] = s2;
    }
    __syncthreads();
    if (t == 0) {
        float m = lg[0];
        for (int i = 1; i < 10; i++) m = fmaxf(m, lg[i]);
        float sm = 0.f;
        for (int i = 0; i < 10; i++) sm += expf(lg[i] - m);
        float ls = logf(sm);
        for (int i = 0; i < 10; i++) out[i] = lg[i] - m - ls;
    }
}

// ---------------- launcher ---------------------------------------------------
extern "C" void kernel_launch(void* const* d_in, const int* in_sizes, int n_in,
                              void* d_out, int out_size) {
    const float* x    = (const float*)d_in[0];
    const int*   ei   = (const int*)d_in[1];
    const float* W1   = (const float*)d_in[2];
    const float* b1   = (const float*)d_in[3];
    const float* W2   = (const float*)d_in[4];
    const float* b2   = (const float*)d_in[5];
    const float* linW = (const float*)d_in[6];
    const float* linb = (const float*)d_in[7];
    const float* attw = (const float*)d_in[8];
    const float* attb = (const float*)d_in[9];
    const float* le1W = (const float*)d_in[10];
    const float* le1b = (const float*)d_in[11];
    const float* le2W = (const float*)d_in[12];
    const float* le3W = (const float*)d_in[13];
    const float* le3b = (const float*)d_in[14];
    const float* l1W  = (const float*)d_in[15];
    const float* l1b  = (const float*)d_in[16];
    const float* l2W  = (const float*)d_in[17];
    const float* l2b  = (const float*)d_in[18];

    float *pA, *pscoreT, *pSpT, *pM2T, *pAc, *pPart;
    float *py, *pmm, *pxq, *pxnew, *ph, *pg, *pro;
    cudaGetSymbolAddress((void**)&pA, g_A);
    cudaGetSymbolAddress((void**)&pscoreT, g_scoreT);
    cudaGetSymbolAddress((void**)&pSpT, g_SpT);
    cudaGetSymbolAddress((void**)&pM2T, g_M2T);
    cudaGetSymbolAddress((void**)&pAc, g_Ac);
    cudaGetSymbolAddress((void**)&pPart, g_part);
    cudaGetSymbolAddress((void**)&py, g_y);
    cudaGetSymbolAddress((void**)&pmm, g_mm);
    cudaGetSymbolAddress((void**)&pxq, g_xq);
    cudaGetSymbolAddress((void**)&pxnew, g_xnew);
    cudaGetSymbolAddress((void**)&ph, g_h);
    cudaGetSymbolAddress((void**)&pg, g_g);
    cudaGetSymbolAddress((void**)&pro, g_ro);

    int n = 2048;
    int ne = in_sizes[1] / 2;

    cudaMemsetAsync(pA, 0, (size_t)n * n * sizeof(float));
    cudaMemsetAsync(pro, 0, 2 * HID * sizeof(float));
    k_scatter<<<(ne + 255) / 256, 256>>>(ei, ne, n);
    k_diag<<<(n + 255) / 256, 256>>>(n);        // A := A1 = A + I

    const float* X = x;
    int f_in = 128;

    for (int lvl = 0; lvl < 3; lvl++) {
        const float* W  = lvl ? W2 : W1;
        const float* bb = lvl ? b2 : b1;
        int k = n / 2;
        int nh = n * HID;
        int rg = (nh + 255) / 256;

        if (lvl == 0) {
            // ---- sparse level-0 path ----
            k_buildnz<<<n, 256>>>(n);                       // nz lists + dinv (block/row)
            k_gemm<false,0><<<dim3(HID/64, n/64, 2), 256>>>(X, W, pPart, n, HID, f_in/2, f_in, HID, HID);
            k_redscale<<<rg, 256>>>(pPart, py, nh, 2);      // y = dinv * (X@W1)
            k_gcn_gather<<<n, 256>>>(bb);
            k_max_gather<<<n, 256>>>();
            k_gemm<false,0><<<dim3(HID/64, n/64, 2), 256>>>(pmm, linW, pPart, n, HID, HID/2, HID, HID, HID);
            k_red<0><<<rg, 256>>>(pPart, pxq, nh, 2);
            k_uv<<<(n * 32 + 255) / 256, 256>>>(linb, attw, n);
            k_softmax_nz<<<n / 8, 256>>>(attb, n);
            k_wsum_gather<<<n, 256>>>();
            k_abc<<<(n * 32 + 255) / 256, 256>>>(le1W, le1b, le2W, le3W, le3b, n);
            k_fit_nz<<<n / 8, 256>>>(n);
            k_sort<<<1, 1024>>>(n, k);
            k_pool<<<k, 256>>>(k);
            k_readout<<<HID, 256>>>(k);
            cudaMemsetAsync(pSpT, 0, (size_t)n * k * sizeof(float));
            k_spscatter<<<k, 256>>>(k);
            k_m2<<<n, 256>>>(k);
            k_acg<<<k, 256>>>(k);
            k_setA<<<(k * k + 255) / 256, 256>>>(k);
        } else {
            // ---- dense path (g_A holds A1) ----
            int S = (n == 1024) ? 4 : 8;
            dim3 gS(HID/64, n/64, S);

            k_dinv<<<n, 256>>>(n);
            // y = dinv * (X@W)
            k_gemm<false,0><<<gS, 256>>>(X, W, pPart, n, HID, HID/S, HID, HID, HID);
            k_redscale<<<rg, 256>>>(pPart, py, nh, S);
            // g = relu(dinv * (A1@y) + b)
            k_gemm<false,0><<<gS, 256>>>(pA, py, pPart, n, HID, n/S, n, HID, HID);
            k_redgcn<<<rg, 256>>>(pPart, bb, pg, nh, S);
            // mm = masked max over A1 != 0
            k_gemm<false,1><<<gS, 256>>>(pA, pg, pPart, n, HID, n/S, n, HID, HID);
            k_red<1><<<rg, 256>>>(pPart, pmm, nh, S);
            // xq = mm@linW
            k_gemm<false,0><<<gS, 256>>>(pmm, linW, pPart, n, HID, HID/S, HID, HID, HID);
            k_red<0><<<rg, 256>>>(pPart, pxq, nh, S);
            k_uv<<<(n * 32 + 255) / 256, 256>>>(linb, attw, n);
            k_softmax<<<n, 256>>>(attb, n);
            // xnew = scoreT@g
            k_gemm<false,0><<<gS, 256>>>(pscoreT, pg, pPart, n, HID, n/S, n, HID, HID);
            k_red<0><<<rg, 256>>>(pPart, pxnew, nh, S);

            k_abc<<<(n * 32 + 255) / 256, 256>>>(le1W, le1b, le2W, le3W, le3b, n);
            k_fit<<<n, 256>>>(n);
            k_sort<<<1, 1024>>>(n, k);
            k_pool<<<k, 256>>>(k);
            k_readout<<<HID, 256>>>(k);

            if (lvl < 2) {
                k_gatherSpT<<<dim3(n / 256, k), 256>>>(n, k);
                // M2T = SpT @ binarize(A1)   (mask = A1 != 0)
                k_gemm<false,2><<<dim3(n/64, k/64, 2), 256>>>(pSpT, pA, pPart, k, n, n/2, n, n, n);
                k_red<0><<<(k * n + 255) / 256, 256>>>(pPart, pM2T, k * n, 2);
                // Ac = SpT @ M2T^T
                k_gemm<true,0><<<dim3(k/64, k/64, 4), 256>>>(pSpT, pM2T, pPart, k, k, n/4, n, n, k);
                k_red<0><<<(k * k + 255) / 256, 256>>>(pPart, pAc, k * k, 4);
                k_setA<<<(k * k + 255) / 256, 256>>>(k);
            }
        }

        X = ph; f_in = HID; n = k;
    }

    k_head<<<1, 256>>>(l1W, l1b, l2W, l2b, (float*)d_out);
}

// round 15
// speedup vs baseline: 3.7823x; 1.1494x over previous
#include <cuda_runtime.h>
#include <math.h>
#include <float.h>

#define NMAX 2048
#define HID  256
#define KMAX (NMAX/2)
#define CAP  256

// ---------------- scratch (device globals) -----------------------------------
// g_A stores A1 = A + I at every level (diag forced to 1).
__device__ float g_A[NMAX*NMAX];
__device__ float g_scoreT[NMAX*NMAX];
__device__ float g_SpT[KMAX*NMAX];
__device__ float g_M2T[KMAX*NMAX];
__device__ float g_Ac[KMAX*KMAX];
__device__ float g_part[4*NMAX*HID];    // split-K partial buffer (2M floats)
__device__ float g_h[NMAX*HID];
__device__ float g_g[NMAX*HID];
__device__ float g_y[NMAX*HID];
__device__ float g_mm[NMAX*HID];
__device__ float g_xq[NMAX*HID];
__device__ float g_xnew[NMAX*HID];
__device__ float g_u[NMAX];
__device__ float g_v[NMAX];
__device__ float g_dinv[NMAX];
__device__ float g_av[NMAX];
__device__ float g_bv[NMAX];
__device__ float g_cv[NMAX];
__device__ float g_fit[NMAX];
__device__ float g_fvals[KMAX];
__device__ int   g_perm[KMAX];
__device__ float g_ro[2*HID];
__device__ int   g_nzidx[NMAX*CAP];
__device__ int   g_nzcnt[NMAX];
__device__ float g_sval[NMAX*CAP];

// ---------------- tiled fp32 GEMM with split-K, double-buffered ---------------
// OP=0: C = A@B chunk (A@B^T if TB). OP=1: masked max (A entry !=0 gates B).
// OP=2: C = A@binarize(B) chunk.
// Block handles K-range [z*Kc,(z+1)*Kc), writes partial to C + z*M*N.
template<bool TB, int OP>
__global__ void __launch_bounds__(256) k_gemm(
    const float* __restrict__ A, const float* __restrict__ B, float* __restrict__ C,
    int M, int N, int Kc, int lda, int ldb, int ldc)
{
    __shared__ float As[2][16][64];
    __shared__ float Bs[2][16][64];
    const int tid = threadIdx.x;
    const int tx = tid & 15, ty = tid >> 4;
    const int m0 = blockIdx.y * 64, n0 = blockIdx.x * 64;
    const int ar = tid >> 2;            // 0..63
    const int ak = (tid & 3) << 2;      // 0,4,8,12
    const int bk = tid >> 4;            // 0..15
    const int bn = (tid & 15) << 2;
    const int kstart = blockIdx.z * Kc;
    float* Cz = C + (size_t)blockIdx.z * M * N;

    const float* Aptr = A + (size_t)(m0 + ar) * lda + kstart + ak;
    const float* Bptr = TB ? (B + (size_t)(n0 + ar) * ldb + kstart + ak)
                           : (B + (size_t)(kstart + bk) * ldb + (n0 + bn));

    float acc[4][4];
#pragma unroll
    for (int i = 0; i < 4; i++)
#pragma unroll
        for (int j = 0; j < 4; j++) acc[i][j] = (OP == 1) ? -FLT_MAX : 0.f;

    // load slab 0 into buffer 0
    {
        float4 av = *(const float4*)Aptr;
        As[0][ak+0][ar] = av.x; As[0][ak+1][ar] = av.y; As[0][ak+2][ar] = av.z; As[0][ak+3][ar] = av.w;
        if (TB) {
            float4 bv = *(const float4*)Bptr;
            Bs[0][ak+0][ar] = bv.x; Bs[0][ak+1][ar] = bv.y; Bs[0][ak+2][ar] = bv.z; Bs[0][ak+3][ar] = bv.w;
        } else {
            float4 bv = *(const float4*)Bptr;
            if (OP == 2) {
                bv.x = (bv.x != 0.f) ? 1.f : 0.f; bv.y = (bv.y != 0.f) ? 1.f : 0.f;
                bv.z = (bv.z != 0.f) ? 1.f : 0.f; bv.w = (bv.w != 0.f) ? 1.f : 0.f;
            }
            *(float4*)&Bs[0][bk][bn] = bv;
        }
    }
    __syncthreads();

    const int nslab = Kc >> 4;
    for (int s = 0; s < nslab; s++) {
        const int buf = s & 1;
        float4 avn, bvn;
        const bool more = (s + 1 < nslab);
        if (more) {
            avn = *(const float4*)(Aptr + (s + 1) * 16);
            if (TB) bvn = *(const float4*)(Bptr + (s + 1) * 16);
            else {
                bvn = *(const float4*)(Bptr + (size_t)(s + 1) * 16 * ldb);
                if (OP == 2) {
                    bvn.x = (bvn.x != 0.f) ? 1.f : 0.f; bvn.y = (bvn.y != 0.f) ? 1.f : 0.f;
                    bvn.z = (bvn.z != 0.f) ? 1.f : 0.f; bvn.w = (bvn.w != 0.f) ? 1.f : 0.f;
                }
            }
        }
#pragma unroll
        for (int kk = 0; kk < 16; kk++) {
            float4 a4 = *(const float4*)&As[buf][kk][ty << 2];
            float4 b4 = *(const float4*)&Bs[buf][kk][tx << 2];
            if (OP != 1) {
                acc[0][0] += a4.x * b4.x; acc[0][1] += a4.x * b4.y; acc[0][2] += a4.x * b4.z; acc[0][3] += a4.x * b4.w;
                acc[1][0] += a4.y * b4.x; acc[1][1] += a4.y * b4.y; acc[1][2] += a4.y * b4.z; acc[1][3] += a4.y * b4.w;
                acc[2][0] += a4.z * b4.x; acc[2][1] += a4.z * b4.y; acc[2][2] += a4.z * b4.z; acc[2][3] += a4.z * b4.w;
                acc[3][0] += a4.w * b4.x; acc[3][1] += a4.w * b4.y; acc[3][2] += a4.w * b4.z; acc[3][3] += a4.w * b4.w;
            } else {
                float am[4] = {a4.x, a4.y, a4.z, a4.w};
                float bm[4] = {b4.x, b4.y, b4.z, b4.w};
#pragma unroll
                for (int i = 0; i < 4; i++)
#pragma unroll
                    for (int j = 0; j < 4; j++)
                        acc[i][j] = (am[i] != 0.f) ? fmaxf(acc[i][j], bm[j]) : acc[i][j];
            }
        }
        if (more) {
            const int nb = buf ^ 1;
            As[nb][ak+0][ar] = avn.x; As[nb][ak+1][ar] = avn.y; As[nb][ak+2][ar] = avn.z; As[nb][ak+3][ar] = avn.w;
            if (TB) {
                Bs[nb][ak+0][ar] = bvn.x; Bs[nb][ak+1][ar] = bvn.y; Bs[nb][ak+2][ar] = bvn.z; Bs[nb][ak+3][ar] = bvn.w;
            } else {
                *(float4*)&Bs[nb][bk][bn] = bvn;
            }
        }
        __syncthreads();
    }
#pragma unroll
    for (int i = 0; i < 4; i++) {
        float4 r; r.x = acc[i][0]; r.y = acc[i][1]; r.z = acc[i][2]; r.w = acc[i][3];
        *(float4*)(Cz + (size_t)(m0 + (ty << 2) + i) * ldc + n0 + (tx << 2)) = r;
    }
}

// reduce S split partials (fixed order). OP=0 sum, OP=1 max.
template<int OP>
__global__ void k_red(const float* __restrict__ part, float* __restrict__ out, int MN, int S) {
    int i = blockIdx.x * 256 + threadIdx.x;
    if (i >= MN) return;
    float v = part[i];
    for (int s = 1; s < S; s++) {
        float w = part[(size_t)s * MN + i];
        v = OP ? fmaxf(v, w) : v + w;
    }
    out[i] = v;
}

// sum partials then scale by dinv[row]: y = dinv * (X@W)
__global__ void k_redscale(const float* __restrict__ part, float* __restrict__ out, int MN, int S) {
    int i = blockIdx.x * 256 + threadIdx.x;
    if (i >= MN) return;
    float v = part[i];
    for (int s = 1; s < S; s++) v += part[(size_t)s * MN + i];
    out[i] = g_dinv[i >> 8] * v;
}

// sum partials of A1@y then GCN epilogue: g = relu(dinv*sum + bias)
__global__ void k_redgcn(const float* __restrict__ part, const float* __restrict__ bias,
                         float* __restrict__ out, int MN, int S) {
    int i = blockIdx.x * 256 + threadIdx.x;
    if (i >= MN) return;
    float v = part[i];
    for (int s = 1; s < S; s++) v += part[(size_t)s * MN + i];
    out[i] = fmaxf(g_dinv[i >> 8] * v + bias[i & 255], 0.f);
}

// ---------------- level-0 sparse kernels --------------------------------------
__global__ void k_scatter(const int* __restrict__ ei, int ne, int n) {
    int e = blockIdx.x * blockDim.x + threadIdx.x;
    if (e < ne) g_A[(size_t)ei[e] * n + ei[ne + e]] = 1.0f;
}

__global__ void k_diag(int n) {
    int i = blockIdx.x * 256 + threadIdx.x;
    if (i < n) g_A[(size_t)i * n + i] = 1.0f;
}

// block per row: compact nonzero indices of A1 row (ascending, deterministic)
__global__ void k_buildnz(int n) {
    __shared__ int sc[256];
    int j = blockIdx.x, t = threadIdx.x;
    const float* row = g_A + (size_t)j * n;
    int seg = n >> 8;
    int base = t * seg;
    float vals[8];
    int cnt = 0;
#pragma unroll
    for (int i = 0; i < 8; i++) {
        float v = (i < seg) ? row[base + i] : 0.f;
        vals[i] = v;
        cnt += (v != 0.f);
    }
    sc[t] = cnt;
    __syncthreads();
    for (int o = 1; o < 256; o <<= 1) {
        int x = (t >= o) ? sc[t - o] : 0;
        __syncthreads();
        sc[t] += x;
        __syncthreads();
    }
    int pos = sc[t] - cnt;
    int total = sc[255];
    int* idx = g_nzidx + (size_t)j * CAP;
#pragma unroll
    for (int i = 0; i < 8; i++) {
        if (vals[i] != 0.f) {
            if (pos < CAP) idx[pos] = base + i;
            pos++;
        }
    }
    if (t == 0) {
        g_nzcnt[j] = (total > CAP) ? CAP : total;
        g_dinv[j] = 1.0f / sqrtf((float)total);
    }
}

__global__ void k_gcn_gather(const float* __restrict__ bias) {
    __shared__ int sidx[CAP];
    int j = blockIdx.x, c = threadIdx.x;
    int cnt = g_nzcnt[j];
    const int* idx = g_nzidx + (size_t)j * CAP;
    for (int t = c; t < cnt; t += 256) sidx[t] = idx[t];
    __syncthreads();
    float acc = 0.f;
#pragma unroll 4
    for (int t = 0; t < cnt; t++) acc += g_y[(size_t)sidx[t] * HID + c];
    g_g[(size_t)j * HID + c] = fmaxf(g_dinv[j] * acc + bias[c], 0.f);
}

__global__ void k_max_gather() {
    __shared__ int sidx[CAP];
    int j = blockIdx.x, c = threadIdx.x;
    int cnt = g_nzcnt[j];
    const int* idx = g_nzidx + (size_t)j * CAP;
    for (int t = c; t < cnt; t += 256) sidx[t] = idx[t];
    __syncthreads();
    float m = -FLT_MAX;
#pragma unroll 4
    for (int t = 0; t < cnt; t++) m = fmaxf(m, g_g[(size_t)sidx[t] * HID + c]);
    g_mm[(size_t)j * HID + c] = m;
}

__global__ void k_uv(const float* __restrict__ linb, const float* __restrict__ attw, int n) {
    int w = (blockIdx.x * blockDim.x + threadIdx.x) >> 5;
    int lane = threadIdx.x & 31;
    if (w >= n) return;
    float su = 0.f, sv = 0.f;
    const float* xq = g_xq + (size_t)w * HID;
    const float* gg = g_g + (size_t)w * HID;
    for (int c = lane; c < HID; c += 32) {
        su += (xq[c] + linb[c]) * attw[c];
        sv += gg[c] * attw[HID + c];
    }
    for (int o = 16; o; o >>= 1) {
        su += __shfl_down_sync(0xffffffffu, su, o);
        sv += __shfl_down_sync(0xffffffffu, sv, o);
    }
    if (lane == 0) { g_u[w] = su; g_v[w] = sv; }
}

__global__ void k_softmax_nz(const float* __restrict__ attb, int n) {
    int w = threadIdx.x >> 5, lane = threadIdx.x & 31;
    int j = blockIdx.x * 8 + w;
    if (j >= n) return;
    int cnt = g_nzcnt[j];
    const int* idx = g_nzidx + (size_t)j * CAP;
    float uj = g_u[j] + attb[0];
    float mx = -FLT_MAX;
    for (int t = lane; t < cnt; t += 32) {
        float r = g_v[idx[t]] + uj; r = (r >= 0.f) ? r : 0.2f * r;
        mx = fmaxf(mx, r);
    }
    for (int o = 16; o; o >>= 1) mx = fmaxf(mx, __shfl_xor_sync(0xffffffffu, mx, o));
    float sm = 0.f;
    for (int t = lane; t < cnt; t += 32) {
        float r = g_v[idx[t]] + uj; r = (r >= 0.f) ? r : 0.2f * r;
        sm += expf(r - mx);
    }
    for (int o = 16; o; o >>= 1) sm += __shfl_xor_sync(0xffffffffu, sm, o);
    float* sval = g_sval + (size_t)j * CAP;
    for (int t = lane; t < cnt; t += 32) {
        float r = g_v[idx[t]] + uj; r = (r >= 0.f) ? r : 0.2f * r;
        sval[t] = expf(r - mx) / sm;
    }
}

__global__ void k_wsum_gather() {
    __shared__ int sidx[CAP];
    __shared__ float sw[CAP];
    int j = blockIdx.x, c = threadIdx.x;
    int cnt = g_nzcnt[j];
    const int* idx = g_nzidx + (size_t)j * CAP;
    const float* sv = g_sval + (size_t)j * CAP;
    for (int t = c; t < cnt; t += 256) { sidx[t] = idx[t]; sw[t] = sv[t]; }
    __syncthreads();
    float acc = 0.f;
#pragma unroll 4
    for (int t = 0; t < cnt; t++) acc += sw[t] * g_g[(size_t)sidx[t] * HID + c];
    g_xnew[(size_t)j * HID + c] = acc;
}

__global__ void k_abc(const float* __restrict__ le1W, const float* __restrict__ le1b,
                      const float* __restrict__ le2W, const float* __restrict__ le3W,
                      const float* __restrict__ le3b, int n) {
    int w = (blockIdx.x * blockDim.x + threadIdx.x) >> 5;
    int lane = threadIdx.x & 31;
    if (w >= n) return;
    const float* xr = g_xnew + (size_t)w * HID;
    float sa = 0.f, sb = 0.f, sc = 0.f;
    for (int c = lane; c < HID; c += 32) {
        float xv = xr[c];
        sa += xv * le1W[c]; sb += xv * le2W[c]; sc += xv * le3W[c];
    }
    for (int o = 16; o; o >>= 1) {
        sa += __shfl_down_sync(0xffffffffu, sa, o);
        sb += __shfl_down_sync(0xffffffffu, sb, o);
        sc += __shfl_down_sync(0xffffffffu, sc, o);
    }
    if (lane == 0) { g_av[w] = sa + le1b[0]; g_bv[w] = sb; g_cv[w] = sc + le3b[0]; }
}

__global__ void k_fit_nz(int n) {
    int w = threadIdx.x >> 5, lane = threadIdx.x & 31;
    int j = blockIdx.x * 8 + w;
    if (j >= n) return;
    int cnt = g_nzcnt[j];
    const int* idx = g_nzidx + (size_t)j * CAP;
    float s = 0.f;
    for (int t = lane; t < cnt; t += 32) s += g_av[idx[t]];
    for (int o = 16; o; o >>= 1) s += __shfl_xor_sync(0xffffffffu, s, o);
    if (lane == 0) {
        float z = s - (float)cnt * g_bv[j] + g_cv[j];
        g_fit[j] = 1.0f / (1.0f + expf(-z));
    }
}

__global__ void k_spscatter(int k) {
    int q = blockIdx.x, t = threadIdx.x;
    int pj = g_perm[q];
    if (t < g_nzcnt[pj])
        g_SpT[(size_t)g_nzidx[(size_t)pj * CAP + t] * k + q] = g_sval[(size_t)pj * CAP + t];
}

__global__ void k_m2(int k) {
    __shared__ int sidx[CAP];
    int j = blockIdx.x, c = threadIdx.x;
    int cnt = g_nzcnt[j];
    const int* idx = g_nzidx + (size_t)j * CAP;
    for (int t = c; t < cnt; t += 256) sidx[t] = idx[t];
    __syncthreads();
    float4 acc = {0.f, 0.f, 0.f, 0.f};
#pragma unroll 2
    for (int t = 0; t < cnt; t++) {
        float4 v = ((const float4*)(g_SpT + (size_t)sidx[t] * k))[c];
        acc.x += v.x; acc.y += v.y; acc.z += v.z; acc.w += v.w;
    }
    ((float4*)(g_M2T + (size_t)j * k))[c] = acc;
}

__global__ void k_acg(int k) {
    __shared__ int sidx[CAP];
    __shared__ float sw[CAP];
    int p = blockIdx.x, c = threadIdx.x;
    int pp = g_perm[p];
    int cnt = g_nzcnt[pp];
    const int* idx = g_nzidx + (size_t)pp * CAP;
    const float* sv = g_sval + (size_t)pp * CAP;
    for (int t = c; t < cnt; t += 256) { sidx[t] = idx[t]; sw[t] = sv[t]; }
    __syncthreads();
    float4 acc = {0.f, 0.f, 0.f, 0.f};
#pragma unroll 2
    for (int t = 0; t < cnt; t++) {
        float w = sw[t];
        float4 v = ((const float4*)(g_M2T + (size_t)sidx[t] * k))[c];
        acc.x += w * v.x; acc.y += w * v.y; acc.z += w * v.z; acc.w += w * v.w;
    }
    ((float4*)(g_Ac + (size_t)p * k))[c] = acc;
}

// ---------------- dense-path kernels (levels >= 1; g_A holds A1) --------------
__global__ void k_dinv(int n) {
    int j = blockIdx.x, tid = threadIdx.x;
    __shared__ float red[256];
    const float* row = g_A + (size_t)j * n;
    float s = 0.f;
    for (int i = tid; i < n; i += 256) s += row[i];
    red[tid] = s; __syncthreads();
    for (int o = 128; o; o >>= 1) { if (tid < o) red[tid] += red[tid + o]; __syncthreads(); }
    if (tid == 0) g_dinv[j] = 1.0f / sqrtf(red[0]);
}

__global__ void k_softmax(const float* __restrict__ attb, int n) {
    int j = blockIdx.x, tid = threadIdx.x;
    __shared__ float red[256];
    __shared__ float s_mx, s_sum;
    const float* mrow = g_A + (size_t)j * n;
    float uj = g_u[j] + attb[0];
    float mx = -FLT_MAX;
    for (int i = tid; i < n; i += 256) {
        if (mrow[i] != 0.f) {
            float r = g_v[i] + uj; r = (r >= 0.f) ? r : 0.2f * r;
            mx = fmaxf(mx, r);
        }
    }
    red[tid] = mx; __syncthreads();
    for (int o = 128; o; o >>= 1) { if (tid < o) red[tid] = fmaxf(red[tid], red[tid + o]); __syncthreads(); }
    if (tid == 0) s_mx = red[0];
    __syncthreads();
    float sm = 0.f;
    for (int i = tid; i < n; i += 256) {
        if (mrow[i] != 0.f) {
            float r = g_v[i] + uj; r = (r >= 0.f) ? r : 0.2f * r;
            sm += expf(r - s_mx);
        }
    }
    red[tid] = sm; __syncthreads();
    for (int o = 128; o; o >>= 1) { if (tid < o) red[tid] += red[tid + o]; __syncthreads(); }
    if (tid == 0) s_sum = red[0];
    __syncthreads();
    float* srow = g_scoreT + (size_t)j * n;
    for (int i = tid; i < n; i += 256) {
        float val = 0.f;
        if (mrow[i] != 0.f) {
            float r = g_v[i] + uj; r = (r >= 0.f) ? r : 0.2f * r;
            val = expf(r - s_mx) / s_sum;
        }
        srow[i] = val;
    }
}

__global__ void k_fit(int n) {
    int j = blockIdx.x, tid = threadIdx.x;
    __shared__ float rs[256], rc[256];
    const float* mrow = g_A + (size_t)j * n;
    float s = 0.f, cn = 0.f;
    for (int i = tid; i < n; i += 256) {
        if (mrow[i] != 0.f) { s += g_av[i]; cn += 1.f; }
    }
    rs[tid] = s; rc[tid] = cn; __syncthreads();
    for (int o = 128; o; o >>= 1) {
        if (tid < o) { rs[tid] += rs[tid + o]; rc[tid] += rc[tid + o]; }
        __syncthreads();
    }
    if (tid == 0) {
        float z = rs[0] - rc[0] * g_bv[j] + g_cv[j];
        g_fit[j] = 1.0f / (1.0f + expf(-z));
    }
}

// bitonic sort on packed 64-bit keys: (fitness_bits << 32) | ~index
// fitness = sigmoid(...) > 0, so positive-float ordering == uint ordering.
__global__ void k_sort(int n, int k) {
    __shared__ unsigned long long sk[NMAX];
    int tid = threadIdx.x;
    for (int i = tid; i < n; i += blockDim.x)
        sk[i] = ((unsigned long long)__float_as_uint(g_fit[i]) << 32) | (unsigned)(~i);
    __syncthreads();
    for (int size = 2; size <= n; size <<= 1) {
        for (int stride = size >> 1; stride > 0; stride >>= 1) {
            for (int i = tid; i < n; i += blockDim.x) {
                int j = i ^ stride;
                if (j > i) {
                    bool desc = ((i & size) == 0);
                    unsigned long long a = sk[i], b = sk[j];
                    if (desc ? (a < b) : (a > b)) { sk[i] = b; sk[j] = a; }
                }
            }
            __syncthreads();
        }
    }
    for (int t = tid; t < k; t += blockDim.x) {
        unsigned long long v = sk[t];
        g_perm[t] = (int)(~(unsigned)v);
        g_fvals[t] = __uint_as_float((unsigned)(v >> 32));
    }
}

__global__ void k_pool(int k) {
    int q = blockIdx.x, c = threadIdx.x;
    g_h[(size_t)q * HID + c] = g_xnew[(size_t)g_perm[q] * HID + c] * g_fvals[q];
}

__global__ void k_readout(int k) {
    __shared__ float rs[256], rm[256];
    int c = blockIdx.x, tid = threadIdx.x;
    float s = 0.f, m = -FLT_MAX;
    for (int q = tid; q < k; q += 256) {
        float v = g_h[(size_t)q * HID + c];
        s += v; m = fmaxf(m, v);
    }
    rs[tid] = s; rm[tid] = m; __syncthreads();
    for (int o = 128; o; o >>= 1) {
        if (tid < o) { rs[tid] += rs[tid + o]; rm[tid] = fmaxf(rm[tid], rm[tid + o]); }
        __syncthreads();
    }
    if (tid == 0) {
        g_ro[c] += rs[0] / (float)k;
        g_ro[HID + c] += rm[0];
    }
}

__global__ void k_gatherSpT(int n, int k) {
    int i = blockIdx.x * 256 + threadIdx.x;
    int q = blockIdx.y;
    g_SpT[(size_t)q * n + i] = g_scoreT[(size_t)g_perm[q] * n + i];
}

// A <- A1 of coarsened graph: off-diag from Ac, diag = 1
__global__ void k_setA(int k) {
    int idx = blockIdx.x * blockDim.x + threadIdx.x;
    if (idx < k * k) {
        int p = idx / k, q = idx - p * k;
        g_A[idx] = (p == q) ? 1.f : g_Ac[idx];
    }
}

__global__ void k_head(const float* __restrict__ l1W, const float* __restrict__ l1b,
                       const float* __restrict__ l2W, const float* __restrict__ l2b,
                       float* __restrict__ out) {
    __shared__ float hid[HID];
    __shared__ float lg[16];
    int t = threadIdx.x;
    float s = l1b[t];
    for (int kk = 0; kk < 2 * HID; kk++) s += g_ro[kk] * l1W[kk * HID + t];
    hid[t] = fmaxf(s, 0.f);
    __syncthreads();
    if (t < 10) {
        float s2 = l2b[t];
        for (int c = 0; c < HID; c++) s2 += hid[c] * l2W[c * 10 + t];
        lg[t] = s2;
    }
    __syncthreads();
    if (t == 0) {
        float m = lg[0];
        for (int i = 1; i < 10; i++) m = fmaxf(m, lg[i]);
        float sm = 0.f;
        for (int i = 0; i < 10; i++) sm += expf(lg[i] - m);
        float ls = logf(sm);
        for (int i = 0; i < 10; i++) out[i] = lg[i] - m - ls;
    }
}

// ---------------- launcher ---------------------------------------------------
extern "C" void kernel_launch(void* const* d_in, const int* in_sizes, int n_in,
                              void* d_out, int out_size) {
    const float* x    = (const float*)d_in[0];
    const int*   ei   = (const int*)d_in[1];
    const float* W1   = (const float*)d_in[2];
    const float* b1   = (const float*)d_in[3];
    const float* W2   = (const float*)d_in[4];
    const float* b2   = (const float*)d_in[5];
    const float* linW = (const float*)d_in[6];
    const float* linb = (const float*)d_in[7];
    const float* attw = (const float*)d_in[8];
    const float* attb = (const float*)d_in[9];
    const float* le1W = (const float*)d_in[10];
    const float* le1b = (const float*)d_in[11];
    const float* le2W = (const float*)d_in[12];
    const float* le3W = (const float*)d_in[13];
    const float* le3b = (const float*)d_in[14];
    const float* l1W  = (const float*)d_in[15];
    const float* l1b  = (const float*)d_in[16];
    const float* l2W  = (const float*)d_in[17];
    const float* l2b  = (const float*)d_in[18];

    float *pA, *pscoreT, *pSpT, *pM2T, *pAc, *pPart;
    float *py, *pmm, *pxq, *pxnew, *ph, *pg, *pro;
    cudaGetSymbolAddress((void**)&pA, g_A);
    cudaGetSymbolAddress((void**)&pscoreT, g_scoreT);
    cudaGetSymbolAddress((void**)&pSpT, g_SpT);
    cudaGetSymbolAddress((void**)&pM2T, g_M2T);
    cudaGetSymbolAddress((void**)&pAc, g_Ac);
    cudaGetSymbolAddress((void**)&pPart, g_part);
    cudaGetSymbolAddress((void**)&py, g_y);
    cudaGetSymbolAddress((void**)&pmm, g_mm);
    cudaGetSymbolAddress((void**)&pxq, g_xq);
    cudaGetSymbolAddress((void**)&pxnew, g_xnew);
    cudaGetSymbolAddress((void**)&ph, g_h);
    cudaGetSymbolAddress((void**)&pg, g_g);
    cudaGetSymbolAddress((void**)&pro, g_ro);

    int n = 2048;
    int ne = in_sizes[1] / 2;

    cudaMemsetAsync(pA, 0, (size_t)n * n * sizeof(float));
    cudaMemsetAsync(pro, 0, 2 * HID * sizeof(float));
    k_scatter<<<(ne + 255) / 256, 256>>>(ei, ne, n);
    k_diag<<<(n + 255) / 256, 256>>>(n);

    const float* X = x;
    int f_in = 128;

    for (int lvl = 0; lvl < 3; lvl++) {
        const float* W  = lvl ? W2 : W1;
        const float* bb = lvl ? b2 : b1;
        int k = n / 2;
        int nh = n * HID;
        int rg = (nh + 255) / 256;

        if (lvl == 0) {
            // ---- sparse level-0 path ----
            k_buildnz<<<n, 256>>>(n);
            k_gemm<false,0><<<dim3(HID/64, n/64, 4), 256>>>(X, W, pPart, n, HID, f_in/4, f_in, HID, HID);
            k_redscale<<<rg, 256>>>(pPart, py, nh, 4);
            k_gcn_gather<<<n, 256>>>(bb);
            k_max_gather<<<n, 256>>>();
            k_gemm<false,0><<<dim3(HID/64, n/64, 4), 256>>>(pmm, linW, pPart, n, HID, HID/4, HID, HID, HID);
            k_red<0><<<rg, 256>>>(pPart, pxq, nh, 4);
            k_uv<<<(n * 32 + 255) / 256, 256>>>(linb, attw, n);
            k_softmax_nz<<<n / 8, 256>>>(attb, n);
            k_wsum_gather<<<n, 256>>>();
            k_abc<<<(n * 32 + 255) / 256, 256>>>(le1W, le1b, le2W, le3W, le3b, n);
            k_fit_nz<<<n / 8, 256>>>(n);
            k_sort<<<1, 1024>>>(n, k);
            k_pool<<<k, 256>>>(k);
            k_readout<<<HID, 256>>>(k);
            cudaMemsetAsync(pSpT, 0, (size_t)n * k * sizeof(float));
            k_spscatter<<<k, 256>>>(k);
            k_m2<<<n, 256>>>(k);
            k_acg<<<k, 256>>>(k);
            k_setA<<<(k * k + 255) / 256, 256>>>(k);
        } else {
            // ---- dense path (g_A holds A1) ----
            const int S = 8;
            dim3 gS(HID/64, n/64, S);

            k_dinv<<<n, 256>>>(n);
            // y = dinv * (X@W)
            k_gemm<false,0><<<gS, 256>>>(X, W, pPart, n, HID, HID/S, HID, HID, HID);
            k_redscale<<<rg, 256>>>(pPart, py, nh, S);
            // g = relu(dinv * (A1@y) + b)
            k_gemm<false,0><<<gS, 256>>>(pA, py, pPart, n, HID, n/S, n, HID, HID);
            k_redgcn<<<rg, 256>>>(pPart, bb, pg, nh, S);
            // mm = masked max over A1 != 0
            k_gemm<false,1><<<gS, 256>>>(pA, pg, pPart, n, HID, n/S, n, HID, HID);
            k_red<1><<<rg, 256>>>(pPart, pmm, nh, S);
            // xq = mm@linW
            k_gemm<false,0><<<gS, 256>>>(pmm, linW, pPart, n, HID, HID/S, HID, HID, HID);
            k_red<0><<<rg, 256>>>(pPart, pxq, nh, S);
            k_uv<<<(n * 32 + 255) / 256, 256>>>(linb, attw, n);
            k_softmax<<<n, 256>>>(attb, n);
            // xnew = scoreT@g
            k_gemm<false,0><<<gS, 256>>>(pscoreT, pg, pPart, n, HID, n/S, n, HID, HID);
            k_red<0><<<rg, 256>>>(pPart, pxnew, nh, S);

            k_abc<<<(n * 32 + 255) / 256, 256>>>(le1W, le1b, le2W, le3W, le3b, n);
            k_fit<<<n, 256>>>(n);
            k_sort<<<1, 1024>>>(n, k);
            k_pool<<<k, 256>>>(k);
            k_readout<<<HID, 256>>>(k);

            if (lvl < 2) {
                k_gatherSpT<<<dim3(n / 256, k), 256>>>(n, k);
                // M2T = SpT @ binarize(A1)
                k_gemm<false,2><<<dim3(n/64, k/64, 4), 256>>>(pSpT, pA, pPart, k, n, n/4, n, n, n);
                k_red<0><<<(k * n + 255) / 256, 256>>>(pPart, pM2T, k * n, 4);
                // Ac = SpT @ M2T^T
                k_gemm<true,0><<<dim3(k/64, k/64, 8), 256>>>(pSpT, pM2T, pPart, k, k, n/8, n, n, k);
                k_red<0><<<(k * k + 255) / 256, 256>>>(pPart, pAc, k * k, 8);
                k_setA<<<(k * k + 255) / 256, 256>>>(k);
            }
        }

        X = ph; f_in = HID; n = k;
    }

    k_head<<<1, 256>>>(l1W, l1b, l2W, l2b, (float*)d_out);
}